// round 11
// baseline (speedup 1.0000x reference)
#include <cuda_runtime.h>
#include <cuda_fp16.h>
#include <math.h>
#include <stdint.h>

#define BSZ 8
#define CCH 512
#define TT  8192
#define NEL (BSZ*CCH*TT)
#define KW  3

// ---- conv tiling: tile = 64 co x 256 t, 4 warps, 3-stage ring, persistent ----
#define MCO 64
#define NTT 256
#define CC  32
#define NCHUNK (CCH/CC)               // 16 chunks per tile
#define ROWB 80
#define A_TILE (64*ROWB)              // 5120
#define BROWS 264
#define B_TILE (BROWS*ROWB)           // 21120
#define SM_BOFF (3*A_TILE)            // 15360
#define STAGE (3*A_TILE + B_TILE)     // 36480
#define NSTAGE 3
#define SM_TOTAL (NSTAGE*STAGE)       // 109440 (2 CTA/SM)
#define CTN 128
#define GRID 304                      // persistent CTAs (2 x 152 SMs on GB300)
#define NTILE (BSZ*(CCH/MCO)*(TT/NTT))// 2048

// ---------------- scratch ------------------------------------------------------
__device__ __half g_actT[NEL];            // [b][t][ci] fp16
__device__ float  g_c1[NEL];              // conv1 out [b][co][t]
__device__ __half g_w1[3*CCH*CCH];        // [tap][co][ci] fp16
__device__ __half g_w2[3*CCH*CCH];
__device__ float  g_a2c[2*CCH];           // exp(alpha) per stage
__device__ float  g_binv[2*CCH];          // 1/(2exp(beta)+eps)

// ---------------- PTX helpers ---------------------------------------------------
__device__ __forceinline__ void cp16(uint32_t dst, const void* src, bool pred) {
    asm volatile("cp.async.ca.shared.global [%0], [%1], 16, %2;"
                 :: "r"(dst), "l"(src), "r"(pred ? 16 : 0));
}
__device__ __forceinline__ void cp_commit() { asm volatile("cp.async.commit_group;"); }
template<int N> __device__ __forceinline__ void cp_wait() {
    asm volatile("cp.async.wait_group %0;" :: "n"(N));
}
__device__ __forceinline__ void ldx4(uint32_t* r, uint32_t addr) {
    asm volatile("ldmatrix.sync.aligned.m8n8.x4.shared.b16 {%0,%1,%2,%3}, [%4];"
                 : "=r"(r[0]), "=r"(r[1]), "=r"(r[2]), "=r"(r[3]) : "r"(addr));
}
__device__ __forceinline__ void mma16816(float* d, const uint32_t* a, const uint32_t* b) {
    asm volatile(
        "mma.sync.aligned.m16n8k16.row.col.f32.f16.f16.f32 "
        "{%0,%1,%2,%3}, {%4,%5,%6,%7}, {%8,%9}, {%0,%1,%2,%3};"
        : "+f"(d[0]), "+f"(d[1]), "+f"(d[2]), "+f"(d[3])
        : "r"(a[0]), "r"(a[1]), "r"(a[2]), "r"(a[3]), "r"(b[0]), "r"(b[1]));
}

// fast sin^2(w): sign-free range reduction (sin^2(w) = sin^2(w - k*pi))
__device__ __forceinline__ float sin2f(float w) {
    float k  = rintf(w * 0.3183098862f);
    float r  = fmaf(k, -3.14159274f, w);
    r        = fmaf(k, 8.742278e-8f, r);
    float r2 = r * r;
    float p  = fmaf(-1.9515296e-4f, r2, 8.3321608e-3f);
    p        = fmaf(p, r2, -1.66665465e-1f);
    p        = fmaf(p, r2, 1.0f);
    float s  = r * p;
    return s * s;
}

// ---------------- kernel 1: weight norm (both convs) -> fp16 [tap][co][ci] ------
__global__ void wnorm_kernel(const float* __restrict__ v1, const float* __restrict__ g1,
                             const float* __restrict__ al1, const float* __restrict__ be1,
                             const float* __restrict__ v2, const float* __restrict__ g2,
                             const float* __restrict__ al2, const float* __restrict__ be2,
                             __half* __restrict__ w1o, __half* __restrict__ w2o,
                             float* __restrict__ a2out, float* __restrict__ binvout)
{
    int set = blockIdx.y;
    const float* v     = set ? v2 : v1;
    const float* g     = set ? g2 : g1;
    const float* alpha = set ? al2 : al1;
    const float* beta  = set ? be2 : be1;
    __half* wsp        = set ? w2o : w1o;
    int co = blockIdx.x;
    const float* vc = v + co * (CCH * KW);
    float s = 0.f;
    for (int i = threadIdx.x; i < CCH * KW; i += 256) { float t = vc[i]; s += t * t; }
    __shared__ float red[256];
    red[threadIdx.x] = s;
    __syncthreads();
    for (int off = 128; off > 0; off >>= 1) {
        if (threadIdx.x < off) red[threadIdx.x] += red[threadIdx.x + off];
        __syncthreads();
    }
    float scale = g[co] / sqrtf(red[0]);
    for (int i = threadIdx.x; i < CCH * KW; i += 256) {
        int ci = i / KW, k = i % KW;
        wsp[((size_t)k * CCH + co) * CCH + ci] = __float2half(vc[i] * scale);
    }
    if (threadIdx.x == 0) {
        a2out[set * CCH + co]   = expf(alpha[co]);                 // w = e^a * u
        binvout[set * CCH + co] = 1.f / (2.f * expf(beta[co]) + 1e-9f);
    }
}

// ---------------- kernel 2: SnakeBeta Activation1d + transpose -> fp16 ----------
// f(u) = u + 2*sin^2(e^a u) * binv ; out = 0.5(f(u0)+f(u1))
#define ATI 64
#define ATT 64
__global__ __launch_bounds__(256)
void snake_actT_kernel(const float* __restrict__ in,
                       const float* __restrict__ a2,
                       const float* __restrict__ binv,
                       __half* __restrict__ oA)
{
    __shared__ float xs[ATI][ATT + 3];
    int tid = threadIdx.x;
    int b = blockIdx.z, ci0 = blockIdx.y * ATI, t0 = blockIdx.x * ATT;
    const float* xb = in + ((size_t)b * CCH + ci0) * TT;

    for (int e = tid; e < ATI * (ATT + 2); e += 256) {
        int r = e / (ATT + 2);
        int c = e - r * (ATT + 2);
        int t = t0 - 1 + c;
        float v;
        if (t < 0)        v = 0.f;
        else if (t >= TT) v = xb[r * TT + (TT - 1)];
        else              v = xb[r * TT + t];
        xs[r][c] = v;
    }
    __syncthreads();

    int w = tid >> 5, l = tid & 31;
    int ciA = 2 * l, ciB = 2 * l + 1;
    float aaA = a2[ci0 + ciA], biA = binv[ci0 + ciA];
    float aaB = a2[ci0 + ciB], biB = binv[ci0 + ciB];
#pragma unroll 2
    for (int s = 0; s < 8; s++) {
        int tl = w * 8 + s;
        int t  = t0 + tl;
        float xmA = xs[ciA][tl], x0A = xs[ciA][tl + 1], xpA = xs[ciA][tl + 2];
        float xmB = xs[ciB][tl], x0B = xs[ciB][tl + 1], xpB = xs[ciB][tl + 2];
        float u0A = (t > 0) ? fmaf(0.25f, xmA, 0.75f * x0A) : x0A;
        float u0B = (t > 0) ? fmaf(0.25f, xmB, 0.75f * x0B) : x0B;
        float u1A = fmaf(0.25f, xpA, 0.75f * x0A);
        float u1B = fmaf(0.25f, xpB, 0.75f * x0B);
        float yA = fmaf(0.5f, u0A + u1A,
                        (sin2f(aaA * u0A) + sin2f(aaA * u1A)) * biA);
        float yB = fmaf(0.5f, u0B + u1B,
                        (sin2f(aaB * u0B) + sin2f(aaB * u1B)) * biB);
        *(__half2*)(oA + ((size_t)b * TT + t) * CCH + ci0 + ciA)
            = __floats2half2_rn(yA, yB);
    }
}

// ---------------- kernel 3: persistent conv via mma.sync fp16 -------------------
__global__ __launch_bounds__(CTN, 2)
void conv_mma_kernel(const __half* __restrict__ aA,
                     const __half* __restrict__ Wsp,
                     const float* __restrict__ bias,
                     const float* __restrict__ resid,
                     float* __restrict__ out)
{
    extern __shared__ char smem[];
    const uint32_t sbase = (uint32_t)__cvta_generic_to_shared(smem);
    const int tid  = threadIdx.x;
    const int wid  = tid >> 5, lane = tid & 31;
    const int gid  = lane >> 2, tig = lane & 3;
    const int bid  = blockIdx.x;

    const int nt = (bid < NTILE) ? ((NTILE - 1 - bid) / GRID + 1) : 0;
    const int nG = nt * NCHUNK;

    float acc[4][8][4];
#pragma unroll
    for (int m = 0; m < 4; m++)
#pragma unroll
        for (int n = 0; n < 8; n++)
#pragma unroll
            for (int q = 0; q < 4; q++) acc[m][n][q] = 0.f;

    auto issueG = [&](int G) {
        int tau = bid + (G >> 4) * GRID;
        if (tau >= NTILE) { cp_commit(); return; }
        int ch  = G & 15;
        int ti  = tau & 31;
        int cog = (tau >> 5) & 7;
        int bb  = tau >> 8;
        int co0 = cog * MCO;
        int t0  = ti * NTT;
        int ci0 = ch * CC;
        const __half* aBase = aA + (size_t)bb * TT * CCH;
        const uint32_t sb = sbase + (uint32_t)(G % NSTAGE) * STAGE;
        for (int u = tid; u < 768 + 1056; u += CTN) {
            if (u < 768) {
                int tile = u >> 8;
                int rem  = u & 255;
                int row  = rem >> 2;
                int seg  = rem & 3;
                const __half* src =
                    Wsp + ((size_t)(tile * CCH + co0 + row)) * CCH + ci0 + seg * 8;
                cp16(sb + tile * A_TILE + row * ROWB + seg * 16, src, true);
            } else {
                int u2  = u - 768;
                int row = u2 >> 2;
                int seg = u2 & 3;
                int t   = t0 - 1 + row;
                bool ok = (t >= 0 && t < TT && row < NTT + 2);
                int tc  = ok ? t : 0;
                const __half* src = aBase + (size_t)tc * CCH + ci0 + seg * 8;
                cp16(sb + SM_BOFF + row * ROWB + seg * 16, src, ok);
            }
        }
        cp_commit();
    };

    issueG(0);
    issueG(1);

    const uint32_t aoffb = (uint32_t)((lane & 15) * ROWB + (lane >> 4) * 16);
    const uint32_t boffb = (uint32_t)(((lane & 7) + ((lane >> 4) << 3) + wid * 64) * ROWB
                                      + ((lane >> 3) & 1) * 16);

    for (int G = 0; G < nG; G++) {
        cp_wait<1>();
        __syncthreads();
        issueG(G + 2);

        const uint32_t sb = sbase + (uint32_t)(G % NSTAGE) * STAGE;
        const uint32_t abase = sb + aoffb;
        const uint32_t bbase = sb + SM_BOFF + boffb;
#pragma unroll
        for (int ks = 0; ks < 2; ks++) {
#pragma unroll
            for (int tap = 0; tap < 3; tap++) {
                uint32_t bq[4][4];
#pragma unroll
                for (int np = 0; np < 4; np++)
                    ldx4(bq[np], bbase + (uint32_t)((np * 16 + tap) * ROWB + ks * 32));
#pragma unroll
                for (int m = 0; m < 4; m++) {
                    uint32_t af[4];
                    ldx4(af, abase + (uint32_t)(tap * A_TILE + m * 16 * ROWB + ks * 32));
#pragma unroll
                    for (int np = 0; np < 4; np++) {
                        mma16816(acc[m][2 * np],     af, &bq[np][0]);
                        mma16816(acc[m][2 * np + 1], af, &bq[np][2]);
                    }
                }
            }
        }

        if ((G & 15) == 15) {
            int tau = bid + (G >> 4) * GRID;
            int ti  = tau & 31;
            int cog = (tau >> 5) & 7;
            int bb  = tau >> 8;
            int co0 = cog * MCO;
            int t0  = ti * NTT;
#pragma unroll
            for (int m = 0; m < 4; m++) {
                int r0 = co0 + m * 16 + gid;
                int r1 = r0 + 8;
                float b0 = bias[r0], b1 = bias[r1];
                size_t o0 = ((size_t)(bb * CCH + r0)) * TT + t0;
                size_t o1 = ((size_t)(bb * CCH + r1)) * TT + t0;
#pragma unroll
                for (int n = 0; n < 8; n++) {
                    int tof = wid * 64 + n * 8 + 2 * tig;
                    float2 v0 = make_float2(acc[m][n][0] + b0, acc[m][n][1] + b0);
                    float2 v1 = make_float2(acc[m][n][2] + b1, acc[m][n][3] + b1);
                    if (resid) {
                        float2 rv0 = *(const float2*)(resid + o0 + tof);
                        float2 rv1 = *(const float2*)(resid + o1 + tof);
                        v0.x += rv0.x; v0.y += rv0.y;
                        v1.x += rv1.x; v1.y += rv1.y;
                    }
                    *(float2*)(out + o0 + tof) = v0;
                    *(float2*)(out + o1 + tof) = v1;
#pragma unroll
                    for (int q = 0; q < 4; q++) acc[m][n][q] = 0.f;
                }
            }
        }
    }
}

// ---------------------------------- launch ---------------------------------------
extern "C" void kernel_launch(void* const* d_in, const int* in_sizes, int n_in,
                              void* d_out, int out_size)
{
    const float* x      = (const float*)d_in[0];
    const float* v1     = (const float*)d_in[1];
    const float* g1     = (const float*)d_in[2];
    const float* bias1  = (const float*)d_in[3];
    const float* v2     = (const float*)d_in[4];
    const float* g2     = (const float*)d_in[5];
    const float* bias2  = (const float*)d_in[6];
    const float* alpha1 = (const float*)d_in[7];
    const float* beta1  = (const float*)d_in[8];
    const float* alpha2 = (const float*)d_in[9];
    const float* beta2  = (const float*)d_in[10];
    float* out = (float*)d_out;

    __half *aA, *w1, *w2;
    float *c1, *a2c, *binv;
    cudaGetSymbolAddress((void**)&aA,   g_actT);
    cudaGetSymbolAddress((void**)&c1,   g_c1);
    cudaGetSymbolAddress((void**)&w1,   g_w1);
    cudaGetSymbolAddress((void**)&w2,   g_w2);
    cudaGetSymbolAddress((void**)&a2c,  g_a2c);
    cudaGetSymbolAddress((void**)&binv, g_binv);

    static bool attr_set = false;
    if (!attr_set) {
        cudaFuncSetAttribute(conv_mma_kernel,
                             cudaFuncAttributeMaxDynamicSharedMemorySize, SM_TOTAL);
        attr_set = true;
    }

    dim3 wgrid(CCH, 2);
    wnorm_kernel<<<wgrid, 256>>>(v1, g1, alpha1, beta1,
                                 v2, g2, alpha2, beta2,
                                 w1, w2, a2c, binv);

    dim3 agrid(TT / ATT, CCH / ATI, BSZ);

    snake_actT_kernel<<<agrid, 256>>>(x, a2c, binv, aA);
    conv_mma_kernel<<<GRID, CTN, SM_TOTAL>>>(aA, w1, bias1, nullptr, c1);
    snake_actT_kernel<<<agrid, 256>>>(c1, a2c + CCH, binv + CCH, aA);
    conv_mma_kernel<<<GRID, CTN, SM_TOTAL>>>(aA, w2, bias2, x, out);
}

// round 12
// speedup vs baseline: 1.0116x; 1.0116x over previous
#include <cuda_runtime.h>
#include <cuda_fp16.h>
#include <math.h>
#include <stdint.h>

#define BSZ 8
#define CCH 512
#define TT  8192
#define NEL (BSZ*CCH*TT)
#define KW  3

// ---- conv tiling: tile = 64 co x 256 t, 4 warps, 3-stage ring, persistent ----
#define MCO 64
#define NTT 256
#define CC  32
#define NCHUNK (CCH/CC)               // 16 chunks per tile
#define ROWB 80
#define A_TILE (64*ROWB)              // 5120
#define BROWS 264
#define B_TILE (BROWS*ROWB)           // 21120
#define SM_BOFF (3*A_TILE)            // 15360
#define STAGE (3*A_TILE + B_TILE)     // 36480
#define NSTAGE 3
#define SM_TOTAL (NSTAGE*STAGE)       // 109440 (2 CTA/SM)
#define CTN 128
#define GRID 296                      // persistent CTAs (2 x 148)
#define NTILE (BSZ*(CCH/MCO)*(TT/NTT))// 2048

// ---------------- scratch ------------------------------------------------------
__device__ __half g_actT[NEL];            // [b][t][ci] fp16
__device__ __half g_c1h[NEL];             // conv1 out [b][co][t] fp16
__device__ __half g_w1[3*CCH*CCH];        // [tap][co][ci] fp16
__device__ __half g_w2[3*CCH*CCH];
__device__ float  g_a2c[2*CCH];           // 2*exp(alpha)
__device__ float  g_binv[2*CCH];          // 1/(2exp(beta)+eps)

// ---------------- PTX helpers ---------------------------------------------------
__device__ __forceinline__ void cp16(uint32_t dst, const void* src, bool pred) {
    asm volatile("cp.async.ca.shared.global [%0], [%1], 16, %2;"
                 :: "r"(dst), "l"(src), "r"(pred ? 16 : 0));
}
__device__ __forceinline__ void cp_commit() { asm volatile("cp.async.commit_group;"); }
template<int N> __device__ __forceinline__ void cp_wait() {
    asm volatile("cp.async.wait_group %0;" :: "n"(N));
}
__device__ __forceinline__ void ldx4(uint32_t* r, uint32_t addr) {
    asm volatile("ldmatrix.sync.aligned.m8n8.x4.shared.b16 {%0,%1,%2,%3}, [%4];"
                 : "=r"(r[0]), "=r"(r[1]), "=r"(r[2]), "=r"(r[3]) : "r"(addr));
}
__device__ __forceinline__ void mma16816(float* d, const uint32_t* a, const uint32_t* b) {
    asm volatile(
        "mma.sync.aligned.m16n8k16.row.col.f32.f16.f16.f32 "
        "{%0,%1,%2,%3}, {%4,%5,%6,%7}, {%8,%9}, {%0,%1,%2,%3};"
        : "+f"(d[0]), "+f"(d[1]), "+f"(d[2]), "+f"(d[3])
        : "r"(a[0]), "r"(a[1]), "r"(a[2]), "r"(a[3]), "r"(b[0]), "r"(b[1]));
}

__device__ __forceinline__ float ld_as_float(const float* p)  { return *p; }
__device__ __forceinline__ float ld_as_float(const __half* p) { return __half2float(*p); }

// ---------------- kernel 1: weight norm (both convs) -> fp16 [tap][co][ci] ------
__global__ void wnorm_kernel(const float* __restrict__ v1, const float* __restrict__ g1,
                             const float* __restrict__ al1, const float* __restrict__ be1,
                             const float* __restrict__ v2, const float* __restrict__ g2,
                             const float* __restrict__ al2, const float* __restrict__ be2,
                             __half* __restrict__ w1o, __half* __restrict__ w2o,
                             float* __restrict__ a2out, float* __restrict__ binvout)
{
    int set = blockIdx.y;
    const float* v     = set ? v2 : v1;
    const float* g     = set ? g2 : g1;
    const float* alpha = set ? al2 : al1;
    const float* beta  = set ? be2 : be1;
    __half* wsp        = set ? w2o : w1o;
    int co = blockIdx.x;
    const float* vc = v + co * (CCH * KW);
    float s = 0.f;
    for (int i = threadIdx.x; i < CCH * KW; i += 256) { float t = vc[i]; s += t * t; }
    __shared__ float red[256];
    red[threadIdx.x] = s;
    __syncthreads();
    for (int off = 128; off > 0; off >>= 1) {
        if (threadIdx.x < off) red[threadIdx.x] += red[threadIdx.x + off];
        __syncthreads();
    }
    float scale = g[co] / sqrtf(red[0]);
    for (int i = threadIdx.x; i < CCH * KW; i += 256) {
        int ci = i / KW, k = i % KW;
        wsp[((size_t)k * CCH + co) * CCH + ci] = __float2half(vc[i] * scale);
    }
    if (threadIdx.x == 0) {
        a2out[set * CCH + co]   = 2.f * expf(alpha[co]);
        binvout[set * CCH + co] = 1.f / (2.f * expf(beta[co]) + 1e-9f);
    }
}

// ---------------- kernel 2: SnakeBeta Activation1d + transpose -> fp16 ----------
// out = 0.5(u0+u1) + (2 - cos(a*u0) - cos(a*u1)) * bi,  a = 2e^alpha, bi = 0.5*binv
// Thread: 2 ci x 8 consecutive t with register-carried neighbors.
#define ATI 64
#define ATT 64
template<typename T>
__global__ __launch_bounds__(256)
void snake_actT_kernel(const T* __restrict__ in,
                       const float* __restrict__ a2,
                       const float* __restrict__ binv,
                       __half* __restrict__ oA)
{
    __shared__ float xs[ATI][ATT + 3];
    int tid = threadIdx.x;
    int b = blockIdx.z, ci0 = blockIdx.y * ATI, t0 = blockIdx.x * ATT;
    const T* xb = in + ((size_t)b * CCH + ci0) * TT;

    for (int e = tid; e < ATI * (ATT + 2); e += 256) {
        int r = e / (ATT + 2);
        int c = e - r * (ATT + 2);
        int t = t0 - 1 + c;
        float v;
        if (t < 0)        v = 0.f;
        else if (t >= TT) v = ld_as_float(xb + r * TT + (TT - 1));
        else              v = ld_as_float(xb + r * TT + t);
        xs[r][c] = v;
    }
    __syncthreads();

    int w = tid >> 5, l = tid & 31;
    int ciA = 2 * l, ciB = 2 * l + 1;
    float aaA = a2[ci0 + ciA], biA = 0.5f * binv[ci0 + ciA];
    float aaB = a2[ci0 + ciB], biB = 0.5f * binv[ci0 + ciB];

    const float* pA = &xs[ciA][w * 8];   // pA[0] = x[t-1] at t = t0 + w*8
    const float* pB = &xs[ciB][w * 8];
    float xmA = pA[0], x0A = pA[1];
    float xmB = pB[0], x0B = pB[1];

    __half* op = oA + ((size_t)b * TT + t0 + w * 8) * CCH + ci0 + ciA;
    int tfirst = t0 + w * 8;

#pragma unroll
    for (int s = 0; s < 8; s++) {
        float xpA = pA[s + 2];
        float xpB = pB[s + 2];
        float u0A = fmaf(0.25f, xmA, 0.75f * x0A);
        float u0B = fmaf(0.25f, xmB, 0.75f * x0B);
        if (tfirst + s == 0) { u0A = x0A; u0B = x0B; }
        float u1A = fmaf(0.25f, xpA, 0.75f * x0A);
        float u1B = fmaf(0.25f, xpB, 0.75f * x0B);
        float cA = 2.f - __cosf(aaA * u0A) - __cosf(aaA * u1A);
        float cB = 2.f - __cosf(aaB * u0B) - __cosf(aaB * u1B);
        float yA = fmaf(0.5f, u0A + u1A, cA * biA);
        float yB = fmaf(0.5f, u0B + u1B, cB * biB);
        *(__half2*)op = __floats2half2_rn(yA, yB);
        op += CCH;
        xmA = x0A; x0A = xpA;
        xmB = x0B; x0B = xpB;
    }
}

// ---------------- kernel 3: persistent conv via mma.sync fp16 -------------------
// OUT_HALF: store fp16 [co][t] (conv1). Else fp32 + residual (conv2).
template<bool OUT_HALF>
__global__ __launch_bounds__(CTN, 2)
void conv_mma_kernel(const __half* __restrict__ aA,
                     const __half* __restrict__ Wsp,
                     const float* __restrict__ bias,
                     const float* __restrict__ resid,
                     void* __restrict__ outv)
{
    extern __shared__ char smem[];
    const uint32_t sbase = (uint32_t)__cvta_generic_to_shared(smem);
    const int tid  = threadIdx.x;
    const int wid  = tid >> 5, lane = tid & 31;
    const int gid  = lane >> 2, tig = lane & 3;
    const int bid  = blockIdx.x;

    const int nt = (bid < NTILE) ? ((NTILE - 1 - bid) / GRID + 1) : 0;
    const int nG = nt * NCHUNK;

    float acc[4][8][4];
#pragma unroll
    for (int m = 0; m < 4; m++)
#pragma unroll
        for (int n = 0; n < 8; n++)
#pragma unroll
            for (int q = 0; q < 4; q++) acc[m][n][q] = 0.f;

    auto issueG = [&](int G) {
        int tau = bid + (G >> 4) * GRID;
        if (tau >= NTILE) { cp_commit(); return; }
        int ch  = G & 15;
        int ti  = tau & 31;
        int cog = (tau >> 5) & 7;
        int bb  = tau >> 8;
        int co0 = cog * MCO;
        int t0  = ti * NTT;
        int ci0 = ch * CC;
        const __half* aBase = aA + (size_t)bb * TT * CCH;
        const uint32_t sb = sbase + (uint32_t)(G % NSTAGE) * STAGE;
        for (int u = tid; u < 768 + 1056; u += CTN) {
            if (u < 768) {
                int tile = u >> 8;
                int rem  = u & 255;
                int row  = rem >> 2;
                int seg  = rem & 3;
                const __half* src =
                    Wsp + ((size_t)(tile * CCH + co0 + row)) * CCH + ci0 + seg * 8;
                cp16(sb + tile * A_TILE + row * ROWB + seg * 16, src, true);
            } else {
                int u2  = u - 768;
                int row = u2 >> 2;
                int seg = u2 & 3;
                int t   = t0 - 1 + row;
                bool ok = (t >= 0 && t < TT && row < NTT + 2);
                int tc  = ok ? t : 0;
                const __half* src = aBase + (size_t)tc * CCH + ci0 + seg * 8;
                cp16(sb + SM_BOFF + row * ROWB + seg * 16, src, ok);
            }
        }
        cp_commit();
    };

    issueG(0);
    issueG(1);

    const uint32_t aoffb = (uint32_t)((lane & 15) * ROWB + (lane >> 4) * 16);
    const uint32_t boffb = (uint32_t)(((lane & 7) + ((lane >> 4) << 3) + wid * 64) * ROWB
                                      + ((lane >> 3) & 1) * 16);

    for (int G = 0; G < nG; G++) {
        cp_wait<1>();
        __syncthreads();
        issueG(G + 2);

        const uint32_t sb = sbase + (uint32_t)(G % NSTAGE) * STAGE;
        const uint32_t abase = sb + aoffb;
        const uint32_t bbase = sb + SM_BOFF + boffb;
#pragma unroll
        for (int ks = 0; ks < 2; ks++) {
#pragma unroll
            for (int tap = 0; tap < 3; tap++) {
                uint32_t bq[4][4];
#pragma unroll
                for (int np = 0; np < 4; np++)
                    ldx4(bq[np], bbase + (uint32_t)((np * 16 + tap) * ROWB + ks * 32));
#pragma unroll
                for (int m = 0; m < 4; m++) {
                    uint32_t af[4];
                    ldx4(af, abase + (uint32_t)(tap * A_TILE + m * 16 * ROWB + ks * 32));
#pragma unroll
                    for (int np = 0; np < 4; np++) {
                        mma16816(acc[m][2 * np],     af, &bq[np][0]);
                        mma16816(acc[m][2 * np + 1], af, &bq[np][2]);
                    }
                }
            }
        }

        if ((G & 15) == 15) {
            int tau = bid + (G >> 4) * GRID;
            int ti  = tau & 31;
            int cog = (tau >> 5) & 7;
            int bb  = tau >> 8;
            int co0 = cog * MCO;
            int t0  = ti * NTT;
#pragma unroll
            for (int m = 0; m < 4; m++) {
                int r0 = co0 + m * 16 + gid;
                int r1 = r0 + 8;
                float b0 = bias[r0], b1 = bias[r1];
                size_t o0 = ((size_t)(bb * CCH + r0)) * TT + t0;
                size_t o1 = ((size_t)(bb * CCH + r1)) * TT + t0;
#pragma unroll
                for (int n = 0; n < 8; n++) {
                    int tof = wid * 64 + n * 8 + 2 * tig;
                    float v00 = acc[m][n][0] + b0, v01 = acc[m][n][1] + b0;
                    float v10 = acc[m][n][2] + b1, v11 = acc[m][n][3] + b1;
                    if (OUT_HALF) {
                        __half* o = (__half*)outv;
                        *(__half2*)(o + o0 + tof) = __floats2half2_rn(v00, v01);
                        *(__half2*)(o + o1 + tof) = __floats2half2_rn(v10, v11);
                    } else {
                        float* o = (float*)outv;
                        float2 rv0 = *(const float2*)(resid + o0 + tof);
                        float2 rv1 = *(const float2*)(resid + o1 + tof);
                        *(float2*)(o + o0 + tof) = make_float2(v00 + rv0.x, v01 + rv0.y);
                        *(float2*)(o + o1 + tof) = make_float2(v10 + rv1.x, v11 + rv1.y);
                    }
#pragma unroll
                    for (int q = 0; q < 4; q++) acc[m][n][q] = 0.f;
                }
            }
        }
    }
}

// ---------------------------------- launch ---------------------------------------
extern "C" void kernel_launch(void* const* d_in, const int* in_sizes, int n_in,
                              void* d_out, int out_size)
{
    const float* x      = (const float*)d_in[0];
    const float* v1     = (const float*)d_in[1];
    const float* g1     = (const float*)d_in[2];
    const float* bias1  = (const float*)d_in[3];
    const float* v2     = (const float*)d_in[4];
    const float* g2     = (const float*)d_in[5];
    const float* bias2  = (const float*)d_in[6];
    const float* alpha1 = (const float*)d_in[7];
    const float* beta1  = (const float*)d_in[8];
    const float* alpha2 = (const float*)d_in[9];
    const float* beta2  = (const float*)d_in[10];
    float* out = (float*)d_out;

    __half *aA, *c1h, *w1, *w2;
    float *a2c, *binv;
    cudaGetSymbolAddress((void**)&aA,   g_actT);
    cudaGetSymbolAddress((void**)&c1h,  g_c1h);
    cudaGetSymbolAddress((void**)&w1,   g_w1);
    cudaGetSymbolAddress((void**)&w2,   g_w2);
    cudaGetSymbolAddress((void**)&a2c,  g_a2c);
    cudaGetSymbolAddress((void**)&binv, g_binv);

    static bool attr_set = false;
    if (!attr_set) {
        cudaFuncSetAttribute(conv_mma_kernel<true>,
                             cudaFuncAttributeMaxDynamicSharedMemorySize, SM_TOTAL);
        cudaFuncSetAttribute(conv_mma_kernel<false>,
                             cudaFuncAttributeMaxDynamicSharedMemorySize, SM_TOTAL);
        attr_set = true;
    }

    dim3 wgrid(CCH, 2);
    wnorm_kernel<<<wgrid, 256>>>(v1, g1, alpha1, beta1,
                                 v2, g2, alpha2, beta2,
                                 w1, w2, a2c, binv);

    dim3 agrid(TT / ATT, CCH / ATI, BSZ);

    snake_actT_kernel<float><<<agrid, 256>>>(x, a2c, binv, aA);
    conv_mma_kernel<true><<<GRID, CTN, SM_TOTAL>>>(aA, w1, bias1, nullptr, c1h);
    snake_actT_kernel<__half><<<agrid, 256>>>(c1h, a2c + CCH, binv + CCH, aA);
    conv_mma_kernel<false><<<GRID, CTN, SM_TOTAL>>>(aA, w2, bias2, x, out);
}

// round 14
// speedup vs baseline: 1.0994x; 1.0867x over previous
#include <cuda_runtime.h>
#include <cuda_fp16.h>
#include <math.h>
#include <stdint.h>

#define BSZ 8
#define CCH 512
#define TT  8192
#define NEL (BSZ*CCH*TT)
#define KW  3

// ---- conv tiling: tile = 64 co x 256 t, 4 warps, 3-stage ring, persistent ----
#define MCO 64
#define NTT 256
#define CC  32
#define NCHUNK (CCH/CC)               // 16 chunks per tile
#define ROWB 80
#define A_TILE (64*ROWB)              // 5120
#define BROWS 264
#define B_TILE (BROWS*ROWB)           // 21120
#define SM_BOFF (3*A_TILE)            // 15360
#define STAGE (3*A_TILE + B_TILE)     // 36480
#define NSTAGE 3
#define SM_TOTAL (NSTAGE*STAGE)       // 109440 (2 CTA/SM)
#define CTN 128
#define GRID 296                      // persistent CTAs (2 x 148)
#define NTILE (BSZ*(CCH/MCO)*(TT/NTT))// 2048
#define EPIT 544                      // epilogue c1 tile row pitch (bytes, 16B-aligned)

// ---------------- scratch ------------------------------------------------------
__device__ __half g_actT[NEL];            // act1 out  [b][t][ci] fp16 (conv1 input)
__device__ __half g_actT2[NEL];           // act2 out  [b][t][ci] fp16 (conv2 input)
__device__ __half g_edge[BSZ*32*4*CCH];   // c1 edge cols [b][k][e][co], e:{0,1,254,255}
__device__ __half g_w1[3*CCH*CCH];        // [tap][co][ci] fp16
__device__ __half g_w2[3*CCH*CCH];
__device__ float  g_a2c[2*CCH];           // 2*exp(alpha)
__device__ float  g_binv[2*CCH];          // 1/(2exp(beta)+eps)

// ---------------- PTX helpers ---------------------------------------------------
__device__ __forceinline__ void cp16(uint32_t dst, const void* src, bool pred) {
    asm volatile("cp.async.ca.shared.global [%0], [%1], 16, %2;"
                 :: "r"(dst), "l"(src), "r"(pred ? 16 : 0));
}
__device__ __forceinline__ void cp_commit() { asm volatile("cp.async.commit_group;"); }
template<int N> __device__ __forceinline__ void cp_wait() {
    asm volatile("cp.async.wait_group %0;" :: "n"(N));
}
__device__ __forceinline__ void ldx4(uint32_t* r, uint32_t addr) {
    asm volatile("ldmatrix.sync.aligned.m8n8.x4.shared.b16 {%0,%1,%2,%3}, [%4];"
                 : "=r"(r[0]), "=r"(r[1]), "=r"(r[2]), "=r"(r[3]) : "r"(addr));
}
__device__ __forceinline__ void mma16816(float* d, const uint32_t* a, const uint32_t* b) {
    asm volatile(
        "mma.sync.aligned.m16n8k16.row.col.f32.f16.f16.f32 "
        "{%0,%1,%2,%3}, {%4,%5,%6,%7}, {%8,%9}, {%0,%1,%2,%3};"
        : "+f"(d[0]), "+f"(d[1]), "+f"(d[2]), "+f"(d[3])
        : "r"(a[0]), "r"(a[1]), "r"(a[2]), "r"(a[3]), "r"(b[0]), "r"(b[1]));
}
__device__ __forceinline__ void sts32(uint32_t addr, uint32_t v) {
    asm volatile("st.shared.b32 [%0], %1;" :: "r"(addr), "r"(v) : "memory");
}
__device__ __forceinline__ uint4 lds128(uint32_t addr) {
    uint4 q;
    asm volatile("ld.shared.v4.b32 {%0,%1,%2,%3}, [%4];"
                 : "=r"(q.x), "=r"(q.y), "=r"(q.z), "=r"(q.w) : "r"(addr));
    return q;
}
__device__ __forceinline__ uint32_t lds16u(uint32_t addr) {
    uint32_t v;
    asm volatile("ld.shared.u16 %0, [%1];" : "=r"(v) : "r"(addr));
    return v;
}
__device__ __forceinline__ float h2f16(uint32_t u) {
    __half_raw r; r.x = (unsigned short)u;
    return __half2float((__half)r);
}
__device__ __forceinline__ void q8f(uint4 q, float* f) {
    float2 t;
    t = __half22float2(*(const __half2*)&q.x); f[0] = t.x; f[1] = t.y;
    t = __half22float2(*(const __half2*)&q.y); f[2] = t.x; f[3] = t.y;
    t = __half22float2(*(const __half2*)&q.z); f[4] = t.x; f[5] = t.y;
    t = __half22float2(*(const __half2*)&q.w); f[6] = t.x; f[7] = t.y;
}

// ---------------- kernel 1: weight norm (both convs) -> fp16 [tap][co][ci] ------
__global__ void wnorm_kernel(const float* __restrict__ v1, const float* __restrict__ g1,
                             const float* __restrict__ al1, const float* __restrict__ be1,
                             const float* __restrict__ v2, const float* __restrict__ g2,
                             const float* __restrict__ al2, const float* __restrict__ be2,
                             __half* __restrict__ w1o, __half* __restrict__ w2o,
                             float* __restrict__ a2out, float* __restrict__ binvout)
{
    int set = blockIdx.y;
    const float* v     = set ? v2 : v1;
    const float* g     = set ? g2 : g1;
    const float* alpha = set ? al2 : al1;
    const float* beta  = set ? be2 : be1;
    __half* wsp        = set ? w2o : w1o;
    int co = blockIdx.x;
    const float* vc = v + co * (CCH * KW);
    float s = 0.f;
    for (int i = threadIdx.x; i < CCH * KW; i += 256) { float t = vc[i]; s += t * t; }
    __shared__ float red[256];
    red[threadIdx.x] = s;
    __syncthreads();
    for (int off = 128; off > 0; off >>= 1) {
        if (threadIdx.x < off) red[threadIdx.x] += red[threadIdx.x + off];
        __syncthreads();
    }
    float scale = g[co] / sqrtf(red[0]);
    for (int i = threadIdx.x; i < CCH * KW; i += 256) {
        int ci = i / KW, k = i % KW;
        wsp[((size_t)k * CCH + co) * CCH + ci] = __float2half(vc[i] * scale);
    }
    if (threadIdx.x == 0) {
        a2out[set * CCH + co]   = 2.f * expf(alpha[co]);
        binvout[set * CCH + co] = 1.f / (2.f * expf(beta[co]) + 1e-9f);
    }
}

// ---------------- kernel 2: SnakeBeta act1 (x fp32 -> actT fp16) ----------------
#define ATI 64
#define ATT 64
__global__ __launch_bounds__(256)
void snake_actT_kernel(const float* __restrict__ in,
                       const float* __restrict__ a2,
                       const float* __restrict__ binv,
                       __half* __restrict__ oA)
{
    __shared__ float xs[ATI][ATT + 3];
    int tid = threadIdx.x;
    int b = blockIdx.z, ci0 = blockIdx.y * ATI, t0 = blockIdx.x * ATT;
    const float* xb = in + ((size_t)b * CCH + ci0) * TT;

    for (int e = tid; e < ATI * (ATT + 2); e += 256) {
        int r = e / (ATT + 2);
        int c = e - r * (ATT + 2);
        int t = t0 - 1 + c;
        float v;
        if (t < 0)        v = 0.f;
        else if (t >= TT) v = xb[r * TT + (TT - 1)];
        else              v = xb[r * TT + t];
        xs[r][c] = v;
    }
    __syncthreads();

    int w = tid >> 5, l = tid & 31;
    int ciA = 2 * l, ciB = 2 * l + 1;
    float aaA = a2[ci0 + ciA], biA = 0.5f * binv[ci0 + ciA];
    float aaB = a2[ci0 + ciB], biB = 0.5f * binv[ci0 + ciB];

    const float* pA = &xs[ciA][w * 8];
    const float* pB = &xs[ciB][w * 8];
    float xmA = pA[0], x0A = pA[1];
    float xmB = pB[0], x0B = pB[1];

    __half* op = oA + ((size_t)b * TT + t0 + w * 8) * CCH + ci0 + ciA;
    int tfirst = t0 + w * 8;

#pragma unroll
    for (int s = 0; s < 8; s++) {
        float xpA = pA[s + 2];
        float xpB = pB[s + 2];
        float u0A = fmaf(0.25f, xmA, 0.75f * x0A);
        float u0B = fmaf(0.25f, xmB, 0.75f * x0B);
        if (tfirst + s == 0) { u0A = x0A; u0B = x0B; }
        float u1A = fmaf(0.25f, xpA, 0.75f * x0A);
        float u1B = fmaf(0.25f, xpB, 0.75f * x0B);
        float cA = 2.f - __cosf(aaA * u0A) - __cosf(aaA * u1A);
        float cB = 2.f - __cosf(aaB * u0B) - __cosf(aaB * u1B);
        float yA = fmaf(0.5f, u0A + u1A, cA * biA);
        float yB = fmaf(0.5f, u0B + u1B, cB * biB);
        *(__half2*)op = __floats2half2_rn(yA, yB);
        op += CCH;
        xmA = x0A; x0A = xpA;
        xmB = x0B; x0B = xpB;
    }
}

// ---------------- kernel 3: persistent conv via mma.sync fp16 -------------------
// FUSE=true : conv1 — epilogue applies SnakeBeta act2 in-smem and writes
//             actOut [b][t][ci] fp16 directly (interior t); edge cols -> edgeOut.
// FUSE=false: conv2 — fp32 + residual to fOut.
template<bool FUSE>
__global__ __launch_bounds__(CTN, 2)
void conv_mma_kernel(const __half* __restrict__ aA,
                     const __half* __restrict__ Wsp,
                     const float* __restrict__ bias,
                     const float* __restrict__ resid,
                     const float* __restrict__ a2,
                     const float* __restrict__ binv,
                     __half* __restrict__ actOut,
                     __half* __restrict__ edgeOut,
                     float* __restrict__ fOut)
{
    extern __shared__ char smem[];
    const uint32_t sbase = (uint32_t)__cvta_generic_to_shared(smem);
    const int tid  = threadIdx.x;
    const int wid  = tid >> 5, lane = tid & 31;
    const int gid  = lane >> 2, tig = lane & 3;
    const int bid  = blockIdx.x;

    const int nt = (bid < NTILE) ? ((NTILE - 1 - bid) / GRID + 1) : 0;
    const int nG = nt * NCHUNK;

    float acc[4][8][4];
#pragma unroll
    for (int m = 0; m < 4; m++)
#pragma unroll
        for (int n = 0; n < 8; n++)
#pragma unroll
            for (int q = 0; q < 4; q++) acc[m][n][q] = 0.f;

    auto issueG = [&](int G) {
        int tau = bid + (G >> 4) * GRID;
        if (tau >= NTILE) { cp_commit(); return; }
        int ch  = G & 15;
        int ti  = tau & 31;
        int cog = (tau >> 5) & 7;
        int bb  = tau >> 8;
        int co0 = cog * MCO;
        int t0  = ti * NTT;
        int ci0 = ch * CC;
        const __half* aBase = aA + (size_t)bb * TT * CCH;
        const uint32_t sb = sbase + (uint32_t)(G % NSTAGE) * STAGE;
        for (int u = tid; u < 768 + 1056; u += CTN) {
            if (u < 768) {
                int tile = u >> 8;
                int rem  = u & 255;
                int row  = rem >> 2;
                int seg  = rem & 3;
                const __half* src =
                    Wsp + ((size_t)(tile * CCH + co0 + row)) * CCH + ci0 + seg * 8;
                cp16(sb + tile * A_TILE + row * ROWB + seg * 16, src, true);
            } else {
                int u2  = u - 768;
                int row = u2 >> 2;
                int seg = u2 & 3;
                int t   = t0 - 1 + row;
                bool ok = (t >= 0 && t < TT && row < NTT + 2);
                int tc  = ok ? t : 0;
                const __half* src = aBase + (size_t)tc * CCH + ci0 + seg * 8;
                cp16(sb + SM_BOFF + row * ROWB + seg * 16, src, ok);
            }
        }
        cp_commit();
    };

    issueG(0);
    issueG(1);

    const uint32_t aoffb = (uint32_t)((lane & 15) * ROWB + (lane >> 4) * 16);
    const uint32_t boffb = (uint32_t)(((lane & 7) + ((lane >> 4) << 3) + wid * 64) * ROWB
                                      + ((lane >> 3) & 1) * 16);

    for (int G = 0; G < nG; G++) {
        cp_wait<1>();
        __syncthreads();
        issueG(G + 2);

        const uint32_t sb = sbase + (uint32_t)(G % NSTAGE) * STAGE;
        const uint32_t abase = sb + aoffb;
        const uint32_t bbase = sb + SM_BOFF + boffb;
#pragma unroll
        for (int ks = 0; ks < 2; ks++) {
#pragma unroll
            for (int tap = 0; tap < 3; tap++) {
                uint32_t bq[4][4];
#pragma unroll
                for (int np = 0; np < 4; np++)
                    ldx4(bq[np], bbase + (uint32_t)((np * 16 + tap) * ROWB + ks * 32));
#pragma unroll
                for (int m = 0; m < 4; m++) {
                    uint32_t af[4];
                    ldx4(af, abase + (uint32_t)(tap * A_TILE + m * 16 * ROWB + ks * 32));
#pragma unroll
                    for (int np = 0; np < 4; np++) {
                        mma16816(acc[m][2 * np],     af, &bq[np][0]);
                        mma16816(acc[m][2 * np + 1], af, &bq[np][2]);
                    }
                }
            }
        }

        if ((G & 15) == 15) {
            int tau = bid + (G >> 4) * GRID;
            int ti  = tau & 31;
            int cog = (tau >> 5) & 7;
            int bb  = tau >> 8;
            int co0 = cog * MCO;
            int t0  = ti * NTT;

            if (FUSE) {
                // ---- phase 0: all warps done reading stage G ----
                __syncthreads();
                const uint32_t ep = sbase + (uint32_t)(G % NSTAGE) * STAGE;
                // ---- phase 1: STS c1 tile fp16 [co][t] + edge column dump ----
#pragma unroll
                for (int m = 0; m < 4; m++) {
                    int r0 = m * 16 + gid, r1 = r0 + 8;
                    float b0 = bias[co0 + r0], b1 = bias[co0 + r1];
#pragma unroll
                    for (int n = 0; n < 8; n++) {
                        int tl = wid * 64 + n * 8 + 2 * tig;
                        float v00 = acc[m][n][0] + b0, v01 = acc[m][n][1] + b0;
                        float v10 = acc[m][n][2] + b1, v11 = acc[m][n][3] + b1;
                        __half2 h0 = __floats2half2_rn(v00, v01);
                        __half2 h1 = __floats2half2_rn(v10, v11);
                        sts32(ep + (uint32_t)(r0 * EPIT + tl * 2), *(uint32_t*)&h0);
                        sts32(ep + (uint32_t)(r1 * EPIT + tl * 2), *(uint32_t*)&h1);
                        if (wid == 0 && n == 0 && tig == 0) {       // t_loc 0,1
                            size_t eb = ((size_t)(bb * 32 + ti) * 4) * CCH;
                            edgeOut[eb + co0 + r0]       = __float2half(v00);
                            edgeOut[eb + CCH + co0 + r0] = __float2half(v01);
                            edgeOut[eb + co0 + r1]       = __float2half(v10);
                            edgeOut[eb + CCH + co0 + r1] = __float2half(v11);
                        }
                        if (wid == 3 && n == 7 && tig == 3) {       // t_loc 254,255
                            size_t eb = ((size_t)(bb * 32 + ti) * 4 + 2) * CCH;
                            edgeOut[eb + co0 + r0]       = __float2half(v00);
                            edgeOut[eb + CCH + co0 + r0] = __float2half(v01);
                            edgeOut[eb + co0 + r1]       = __float2half(v10);
                            edgeOut[eb + CCH + co0 + r1] = __float2half(v11);
                        }
                    }
                }
                __syncthreads();
                // ---- phase 2: act2 on tile, transposed coalesced store ----
                {
                    int tb  = tid >> 3;            // t-block (16 t each)
                    int cig = (tid & 7) * 8;       // 8 ci rows
                    uint32_t outw[16][4];
#pragma unroll
                    for (int j = 0; j < 4; j++) {
                        int ra = cig + 2 * j;
                        uint32_t pa = ep + (uint32_t)(ra * EPIT + tb * 32);
                        uint32_t pb = pa + EPIT;
                        float fa[18], fb[18];
                        q8f(lds128(pa), fa + 1); q8f(lds128(pa + 16), fa + 9);
                        q8f(lds128(pb), fb + 1); q8f(lds128(pb + 16), fb + 9);
                        fa[0]  = h2f16(lds16u(tb ? pa - 2 : pa));
                        fb[0]  = h2f16(lds16u(tb ? pb - 2 : pb));
                        fa[17] = h2f16(lds16u(pa + 32));
                        fb[17] = h2f16(lds16u(pb + 32));
                        float aaA = a2[co0 + ra],     biA = 0.5f * binv[co0 + ra];
                        float aaB = a2[co0 + ra + 1], biB = 0.5f * binv[co0 + ra + 1];
#pragma unroll
                        for (int s = 0; s < 16; s++) {
                            float u0A = fmaf(0.25f, fa[s],     0.75f * fa[s + 1]);
                            float u1A = fmaf(0.25f, fa[s + 2], 0.75f * fa[s + 1]);
                            float u0B = fmaf(0.25f, fb[s],     0.75f * fb[s + 1]);
                            float u1B = fmaf(0.25f, fb[s + 2], 0.75f * fb[s + 1]);
                            float yA = fmaf(0.5f, u0A + u1A,
                                (2.f - __cosf(aaA * u0A) - __cosf(aaA * u1A)) * biA);
                            float yB = fmaf(0.5f, u0B + u1B,
                                (2.f - __cosf(aaB * u0B) - __cosf(aaB * u1B)) * biB);
                            __half2 hp = __floats2half2_rn(yA, yB);
                            outw[s][j] = *(uint32_t*)&hp;
                        }
                    }
#pragma unroll
                    for (int s = 0; s < 16; s++) {
                        int tl = tb * 16 + s;
                        if (tl != 0 && tl != 255) {
                            __half* dst = actOut + ((size_t)bb * TT + t0 + tl) * CCH
                                          + co0 + cig;
                            *(uint4*)dst = make_uint4(outw[s][0], outw[s][1],
                                                      outw[s][2], outw[s][3]);
                        }
                    }
                }
                // ---- zero accumulators for next tile ----
#pragma unroll
                for (int m = 0; m < 4; m++)
#pragma unroll
                    for (int n = 0; n < 8; n++)
#pragma unroll
                        for (int q = 0; q < 4; q++) acc[m][n][q] = 0.f;
            } else {
                // ---- conv2 epilogue: fp32 + residual ----
#pragma unroll
                for (int m = 0; m < 4; m++) {
                    int r0 = co0 + m * 16 + gid;
                    int r1 = r0 + 8;
                    float b0 = bias[r0], b1 = bias[r1];
                    size_t o0 = ((size_t)(bb * CCH + r0)) * TT + t0;
                    size_t o1 = ((size_t)(bb * CCH + r1)) * TT + t0;
#pragma unroll
                    for (int n = 0; n < 8; n++) {
                        int tof = wid * 64 + n * 8 + 2 * tig;
                        float2 rv0 = *(const float2*)(resid + o0 + tof);
                        float2 rv1 = *(const float2*)(resid + o1 + tof);
                        *(float2*)(fOut + o0 + tof) =
                            make_float2(acc[m][n][0] + b0 + rv0.x,
                                        acc[m][n][1] + b0 + rv0.y);
                        *(float2*)(fOut + o1 + tof) =
                            make_float2(acc[m][n][2] + b1 + rv1.x,
                                        acc[m][n][3] + b1 + rv1.y);
#pragma unroll
                        for (int q = 0; q < 4; q++) acc[m][n][q] = 0.f;
                    }
                }
            }
        }
    }
}

// ---------------- kernel 4: act2 for tile-edge columns --------------------------
__global__ void edge_act_kernel(const __half* __restrict__ edge,
                                const float* __restrict__ a2,
                                const float* __restrict__ binv,
                                __half* __restrict__ actOut)
{
    int k = blockIdx.x, b = blockIdx.y;
    int ci = threadIdx.x * 2;
    float2 aa = make_float2(a2[ci], a2[ci + 1]);
    float2 bi = make_float2(0.5f * binv[ci], 0.5f * binv[ci + 1]);

    auto ld2 = [&](int kk, int e) {
        const __half2* p = (const __half2*)(edge + ((size_t)((b * 32 + kk) * 4 + e)) * CCH + ci);
        return __half22float2(*p);
    };
    auto snake = [&](float2 xm, float2 x0, float2 xp, bool first) {
        float2 u0, u1, y;
        u0.x = first ? x0.x : fmaf(0.25f, xm.x, 0.75f * x0.x);
        u0.y = first ? x0.y : fmaf(0.25f, xm.y, 0.75f * x0.y);
        u1.x = fmaf(0.25f, xp.x, 0.75f * x0.x);
        u1.y = fmaf(0.25f, xp.y, 0.75f * x0.y);
        y.x = fmaf(0.5f, u0.x + u1.x,
                   (2.f - __cosf(aa.x * u0.x) - __cosf(aa.x * u1.x)) * bi.x);
        y.y = fmaf(0.5f, u0.y + u1.y,
                   (2.f - __cosf(aa.y * u0.y) - __cosf(aa.y * u1.y)) * bi.y);
        return y;
    };

    // t = k*256  (e0; xm = prev tile e3)
    {
        float2 x0 = ld2(k, 0), xp = ld2(k, 1);
        float2 xm = (k > 0) ? ld2(k - 1, 3) : x0;
        float2 y = snake(xm, x0, xp, k == 0);
        *(__half2*)(actOut + ((size_t)b * TT + k * 256) * CCH + ci) =
            __floats2half2_rn(y.x, y.y);
    }
    // t = k*256 + 255  (e3; xp = next tile e0, clamp at global end)
    {
        float2 xm = ld2(k, 2), x0 = ld2(k, 3);
        float2 xp = (k < 31) ? ld2(k + 1, 0) : x0;
        float2 y = snake(xm, x0, xp, false);
        *(__half2*)(actOut + ((size_t)b * TT + k * 256 + 255) * CCH + ci) =
            __floats2half2_rn(y.x, y.y);
    }
}

// ---------------------------------- launch ---------------------------------------
extern "C" void kernel_launch(void* const* d_in, const int* in_sizes, int n_in,
                              void* d_out, int out_size)
{
    const float* x      = (const float*)d_in[0];
    const float* v1     = (const float*)d_in[1];
    const float* g1     = (const float*)d_in[2];
    const float* bias1  = (const float*)d_in[3];
    const float* v2     = (const float*)d_in[4];
    const float* g2     = (const float*)d_in[5];
    const float* bias2  = (const float*)d_in[6];
    const float* alpha1 = (const float*)d_in[7];
    const float* beta1  = (const float*)d_in[8];
    const float* alpha2 = (const float*)d_in[9];
    const float* beta2  = (const float*)d_in[10];
    float* out = (float*)d_out;

    __half *aA, *aB, *eg, *w1, *w2;
    float *a2c, *binv;
    cudaGetSymbolAddress((void**)&aA,   g_actT);
    cudaGetSymbolAddress((void**)&aB,   g_actT2);
    cudaGetSymbolAddress((void**)&eg,   g_edge);
    cudaGetSymbolAddress((void**)&w1,   g_w1);
    cudaGetSymbolAddress((void**)&w2,   g_w2);
    cudaGetSymbolAddress((void**)&a2c,  g_a2c);
    cudaGetSymbolAddress((void**)&binv, g_binv);

    static bool attr_set = false;
    if (!attr_set) {
        cudaFuncSetAttribute(conv_mma_kernel<true>,
                             cudaFuncAttributeMaxDynamicSharedMemorySize, SM_TOTAL);
        cudaFuncSetAttribute(conv_mma_kernel<false>,
                             cudaFuncAttributeMaxDynamicSharedMemorySize, SM_TOTAL);
        attr_set = true;
    }

    dim3 wgrid(CCH, 2);
    wnorm_kernel<<<wgrid, 256>>>(v1, g1, alpha1, beta1,
                                 v2, g2, alpha2, beta2,
                                 w1, w2, a2c, binv);

    dim3 agrid(TT / ATT, CCH / ATI, BSZ);
    snake_actT_kernel<<<agrid, 256>>>(x, a2c, binv, aA);

    // conv1 (+fused act2 interior) -> actT2 ; edge cols -> g_edge
    conv_mma_kernel<true><<<GRID, CTN, SM_TOTAL>>>(
        aA, w1, bias1, nullptr, a2c + CCH, binv + CCH, aB, eg, nullptr);

    // act2 edge columns
    edge_act_kernel<<<dim3(32, BSZ), 256>>>(eg, a2c + CCH, binv + CCH, aB);

    // conv2 + residual -> out
    conv_mma_kernel<false><<<GRID, CTN, SM_TOTAL>>>(
        aB, w2, bias2, x, nullptr, nullptr, nullptr, nullptr, out);
}

// round 15
// speedup vs baseline: 1.1361x; 1.0334x over previous
#include <cuda_runtime.h>
#include <cuda_fp16.h>
#include <math.h>
#include <stdint.h>

#define BSZ 8
#define CCH 512
#define TT  8192
#define NEL (BSZ*CCH*TT)
#define KW  3

// ---- conv tiling: tile = 64 co x 256 t, 4 warps, 3-stage ring, persistent ----
#define MCO 64
#define NTT 256
#define CC  32
#define NCHUNK (CCH/CC)               // 16 chunks per tile
#define ROWB 80
#define A_TILE (64*ROWB)              // 5120
#define BROWS 264
#define B_TILE (BROWS*ROWB)           // 21120
#define SM_BOFF (3*A_TILE)            // 15360
#define STAGE (3*A_TILE + B_TILE)     // 36480
#define NSTAGE 3
#define SM_TOTAL (NSTAGE*STAGE)       // 109440 (2 CTA/SM)
#define CTN 128
#define GRID 296                      // persistent CTAs (2 x 148)
#define NTILE (BSZ*(CCH/MCO)*(TT/NTT))// 2048
#define EPIT 544                      // epilogue c1 tile row pitch (bytes, 16B-aligned)

// ---------------- scratch ------------------------------------------------------
__device__ __half g_actT[NEL];            // act1 out  [b][t][ci] fp16 (conv1 input)
__device__ __half g_actT2[NEL];           // act2 out  [b][t][ci] fp16 (conv2 input)
__device__ __half g_edge[BSZ*32*4*CCH];   // c1 edge cols [b][k][e][co], e:{0,1,254,255}
__device__ __half g_w1[3*CCH*CCH];        // [tap][co][ci] fp16
__device__ __half g_w2[3*CCH*CCH];
__device__ float  g_a2c[2*CCH];           // 2*exp(alpha)
__device__ float  g_binv[2*CCH];          // 1/(2exp(beta)+eps)

// ---------------- PTX helpers ---------------------------------------------------
__device__ __forceinline__ void cp16(uint32_t dst, const void* src, bool pred) {
    asm volatile("cp.async.ca.shared.global [%0], [%1], 16, %2;"
                 :: "r"(dst), "l"(src), "r"(pred ? 16 : 0));
}
__device__ __forceinline__ void cp_commit() { asm volatile("cp.async.commit_group;"); }
template<int N> __device__ __forceinline__ void cp_wait() {
    asm volatile("cp.async.wait_group %0;" :: "n"(N));
}
__device__ __forceinline__ void ldx4(uint32_t* r, uint32_t addr) {
    asm volatile("ldmatrix.sync.aligned.m8n8.x4.shared.b16 {%0,%1,%2,%3}, [%4];"
                 : "=r"(r[0]), "=r"(r[1]), "=r"(r[2]), "=r"(r[3]) : "r"(addr));
}
__device__ __forceinline__ void mma16816(float* d, const uint32_t* a, const uint32_t* b) {
    asm volatile(
        "mma.sync.aligned.m16n8k16.row.col.f32.f16.f16.f32 "
        "{%0,%1,%2,%3}, {%4,%5,%6,%7}, {%8,%9}, {%0,%1,%2,%3};"
        : "+f"(d[0]), "+f"(d[1]), "+f"(d[2]), "+f"(d[3])
        : "r"(a[0]), "r"(a[1]), "r"(a[2]), "r"(a[3]), "r"(b[0]), "r"(b[1]));
}
__device__ __forceinline__ void sts32(uint32_t addr, uint32_t v) {
    asm volatile("st.shared.b32 [%0], %1;" :: "r"(addr), "r"(v) : "memory");
}
__device__ __forceinline__ uint4 lds128(uint32_t addr) {
    uint4 q;
    asm volatile("ld.shared.v4.b32 {%0,%1,%2,%3}, [%4];"
                 : "=r"(q.x), "=r"(q.y), "=r"(q.z), "=r"(q.w) : "r"(addr));
    return q;
}
__device__ __forceinline__ uint32_t lds16u(uint32_t addr) {
    uint32_t v;
    asm volatile("ld.shared.u16 %0, [%1];" : "=r"(v) : "r"(addr));
    return v;
}
__device__ __forceinline__ float h2f16(uint32_t u) {
    __half_raw r; r.x = (unsigned short)u;
    return __half2float((__half)r);
}
__device__ __forceinline__ void q8f(uint4 q, float* f) {
    float2 t;
    t = __half22float2(*(const __half2*)&q.x); f[0] = t.x; f[1] = t.y;
    t = __half22float2(*(const __half2*)&q.y); f[2] = t.x; f[3] = t.y;
    t = __half22float2(*(const __half2*)&q.z); f[4] = t.x; f[5] = t.y;
    t = __half22float2(*(const __half2*)&q.w); f[6] = t.x; f[7] = t.y;
}

// ---------------- kernel 1: weight norm (both convs) -> fp16 [tap][co][ci] ------
__global__ void wnorm_kernel(const float* __restrict__ v1, const float* __restrict__ g1,
                             const float* __restrict__ al1, const float* __restrict__ be1,
                             const float* __restrict__ v2, const float* __restrict__ g2,
                             const float* __restrict__ al2, const float* __restrict__ be2,
                             __half* __restrict__ w1o, __half* __restrict__ w2o,
                             float* __restrict__ a2out, float* __restrict__ binvout)
{
    int set = blockIdx.y;
    const float* v     = set ? v2 : v1;
    const float* g     = set ? g2 : g1;
    const float* alpha = set ? al2 : al1;
    const float* beta  = set ? be2 : be1;
    __half* wsp        = set ? w2o : w1o;
    int co = blockIdx.x;
    const float* vc = v + co * (CCH * KW);
    float s = 0.f;
    for (int i = threadIdx.x; i < CCH * KW; i += 256) { float t = vc[i]; s += t * t; }
    __shared__ float red[256];
    red[threadIdx.x] = s;
    __syncthreads();
    for (int off = 128; off > 0; off >>= 1) {
        if (threadIdx.x < off) red[threadIdx.x] += red[threadIdx.x + off];
        __syncthreads();
    }
    float scale = g[co] / sqrtf(red[0]);
    for (int i = threadIdx.x; i < CCH * KW; i += 256) {
        int ci = i / KW, k = i % KW;
        wsp[((size_t)k * CCH + co) * CCH + ci] = __float2half(vc[i] * scale);
    }
    if (threadIdx.x == 0) {
        a2out[set * CCH + co]   = 2.f * expf(alpha[co]);
        binvout[set * CCH + co] = 1.f / (2.f * expf(beta[co]) + 1e-9f);
    }
}

// ---------------- kernel 2: SnakeBeta act1 (x fp32 -> actT fp16) ----------------
#define ATI 64
#define ATT 64
__global__ __launch_bounds__(256)
void snake_actT_kernel(const float* __restrict__ in,
                       const float* __restrict__ a2,
                       const float* __restrict__ binv,
                       __half* __restrict__ oA)
{
    __shared__ float xs[ATI][ATT + 3];
    int tid = threadIdx.x;
    int b = blockIdx.z, ci0 = blockIdx.y * ATI, t0 = blockIdx.x * ATT;
    const float* xb = in + ((size_t)b * CCH + ci0) * TT;

    // division-free staging: warp covers 4 rows x 8 cols (full 32B sectors)
    {
        int rr = tid >> 3;          // 0..31
        int cc = tid & 7;
#pragma unroll
        for (int rb = 0; rb < ATI; rb += 32) {
            int r = rb + rr;
            const float* row = xb + r * TT;
#pragma unroll
            for (int c = cc; c < ATT + 2; c += 8) {
                int t = t0 - 1 + c;
                float v;
                if (t < 0)        v = 0.f;
                else if (t >= TT) v = row[TT - 1];
                else              v = row[t];
                xs[r][c] = v;
            }
        }
    }
    __syncthreads();

    int w = tid >> 5, l = tid & 31;
    int ciA = 2 * l, ciB = 2 * l + 1;
    float aaA = a2[ci0 + ciA], biA = 0.5f * binv[ci0 + ciA];
    float aaB = a2[ci0 + ciB], biB = 0.5f * binv[ci0 + ciB];

    const float* pA = &xs[ciA][w * 8];
    const float* pB = &xs[ciB][w * 8];
    float xmA = pA[0], x0A = pA[1];
    float xmB = pB[0], x0B = pB[1];

    __half* op = oA + ((size_t)b * TT + t0 + w * 8) * CCH + ci0 + ciA;
    int tfirst = t0 + w * 8;

#pragma unroll
    for (int s = 0; s < 8; s++) {
        float xpA = pA[s + 2];
        float xpB = pB[s + 2];
        float u0A = fmaf(0.25f, xmA, 0.75f * x0A);
        float u0B = fmaf(0.25f, xmB, 0.75f * x0B);
        if (tfirst + s == 0) { u0A = x0A; u0B = x0B; }
        float u1A = fmaf(0.25f, xpA, 0.75f * x0A);
        float u1B = fmaf(0.25f, xpB, 0.75f * x0B);
        float cA = 2.f - __cosf(aaA * u0A) - __cosf(aaA * u1A);
        float cB = 2.f - __cosf(aaB * u0B) - __cosf(aaB * u1B);
        float yA = fmaf(0.5f, u0A + u1A, cA * biA);
        float yB = fmaf(0.5f, u0B + u1B, cB * biB);
        *(__half2*)op = __floats2half2_rn(yA, yB);
        op += CCH;
        xmA = x0A; x0A = xpA;
        xmB = x0B; x0B = xpB;
    }
}

// ---------------- kernel 3: persistent conv via mma.sync fp16 -------------------
// FUSE=true : conv1 — epilogue applies SnakeBeta act2 in-smem and writes
//             actOut [b][t][ci] fp16 directly; edge cols via edgeOut + edge kernel
//             (edge kernel overwrites t%256==0/255 columns afterwards).
// FUSE=false: conv2 — fp32 + residual to fOut.
template<bool FUSE>
__global__ __launch_bounds__(CTN, 2)
void conv_mma_kernel(const __half* __restrict__ aA,
                     const __half* __restrict__ Wsp,
                     const float* __restrict__ bias,
                     const float* __restrict__ resid,
                     const float* __restrict__ a2,
                     const float* __restrict__ binv,
                     __half* __restrict__ actOut,
                     __half* __restrict__ edgeOut,
                     float* __restrict__ fOut)
{
    extern __shared__ char smem[];
    const uint32_t sbase = (uint32_t)__cvta_generic_to_shared(smem);
    const int tid  = threadIdx.x;
    const int wid  = tid >> 5, lane = tid & 31;
    const int gid  = lane >> 2, tig = lane & 3;
    const int bid  = blockIdx.x;

    const int nt = (bid < NTILE) ? ((NTILE - 1 - bid) / GRID + 1) : 0;
    const int nG = nt * NCHUNK;

    float acc[4][8][4];
#pragma unroll
    for (int m = 0; m < 4; m++)
#pragma unroll
        for (int n = 0; n < 8; n++)
#pragma unroll
            for (int q = 0; q < 4; q++) acc[m][n][q] = 0.f;

    auto issueG = [&](int G) {
        int tau = bid + (G >> 4) * GRID;
        if (tau >= NTILE) { cp_commit(); return; }
        int ch  = G & 15;
        int ti  = tau & 31;
        int cog = (tau >> 5) & 7;
        int bb  = tau >> 8;
        int co0 = cog * MCO;
        int t0  = ti * NTT;
        int ci0 = ch * CC;
        const __half* aBase = aA + (size_t)bb * TT * CCH;
        const uint32_t sb = sbase + (uint32_t)(G % NSTAGE) * STAGE;
        for (int u = tid; u < 768 + 1056; u += CTN) {
            if (u < 768) {
                int tile = u >> 8;
                int rem  = u & 255;
                int row  = rem >> 2;
                int seg  = rem & 3;
                const __half* src =
                    Wsp + ((size_t)(tile * CCH + co0 + row)) * CCH + ci0 + seg * 8;
                cp16(sb + tile * A_TILE + row * ROWB + seg * 16, src, true);
            } else {
                int u2  = u - 768;
                int row = u2 >> 2;
                int seg = u2 & 3;
                int t   = t0 - 1 + row;
                bool ok = (t >= 0 && t < TT && row < NTT + 2);
                int tc  = ok ? t : 0;
                const __half* src = aBase + (size_t)tc * CCH + ci0 + seg * 8;
                cp16(sb + SM_BOFF + row * ROWB + seg * 16, src, ok);
            }
        }
        cp_commit();
    };

    issueG(0);
    issueG(1);

    const uint32_t aoffb = (uint32_t)((lane & 15) * ROWB + (lane >> 4) * 16);
    const uint32_t boffb = (uint32_t)(((lane & 7) + ((lane >> 4) << 3) + wid * 64) * ROWB
                                      + ((lane >> 3) & 1) * 16);

    for (int G = 0; G < nG; G++) {
        cp_wait<1>();
        __syncthreads();
        issueG(G + 2);

        const uint32_t sb = sbase + (uint32_t)(G % NSTAGE) * STAGE;
        const uint32_t abase = sb + aoffb;
        const uint32_t bbase = sb + SM_BOFF + boffb;
#pragma unroll
        for (int ks = 0; ks < 2; ks++) {
#pragma unroll
            for (int tap = 0; tap < 3; tap++) {
                uint32_t bq[4][4];
#pragma unroll
                for (int np = 0; np < 4; np++)
                    ldx4(bq[np], bbase + (uint32_t)((np * 16 + tap) * ROWB + ks * 32));
#pragma unroll
                for (int m = 0; m < 4; m++) {
                    uint32_t af[4];
                    ldx4(af, abase + (uint32_t)(tap * A_TILE + m * 16 * ROWB + ks * 32));
#pragma unroll
                    for (int np = 0; np < 4; np++) {
                        mma16816(acc[m][2 * np],     af, &bq[np][0]);
                        mma16816(acc[m][2 * np + 1], af, &bq[np][2]);
                    }
                }
            }
        }

        if ((G & 15) == 15) {
            int tau = bid + (G >> 4) * GRID;
            int ti  = tau & 31;
            int cog = (tau >> 5) & 7;
            int bb  = tau >> 8;
            int co0 = cog * MCO;
            int t0  = ti * NTT;

            if (FUSE) {
                // ---- phase 0: all warps done reading stage G ----
                __syncthreads();
                const uint32_t ep = sbase + (uint32_t)(G % NSTAGE) * STAGE;
                // ---- phase 1: STS c1 tile fp16 [co][t] + edge column dump ----
#pragma unroll
                for (int m = 0; m < 4; m++) {
                    int r0 = m * 16 + gid, r1 = r0 + 8;
                    float b0 = bias[co0 + r0], b1 = bias[co0 + r1];
#pragma unroll
                    for (int n = 0; n < 8; n++) {
                        int tl = wid * 64 + n * 8 + 2 * tig;
                        float v00 = acc[m][n][0] + b0, v01 = acc[m][n][1] + b0;
                        float v10 = acc[m][n][2] + b1, v11 = acc[m][n][3] + b1;
                        __half2 h0 = __floats2half2_rn(v00, v01);
                        __half2 h1 = __floats2half2_rn(v10, v11);
                        sts32(ep + (uint32_t)(r0 * EPIT + tl * 2), *(uint32_t*)&h0);
                        sts32(ep + (uint32_t)(r1 * EPIT + tl * 2), *(uint32_t*)&h1);
                        if (wid == 0 && n == 0 && tig == 0) {       // t_loc 0,1
                            size_t eb = ((size_t)(bb * 32 + ti) * 4) * CCH;
                            edgeOut[eb + co0 + r0]       = __float2half(v00);
                            edgeOut[eb + CCH + co0 + r0] = __float2half(v01);
                            edgeOut[eb + co0 + r1]       = __float2half(v10);
                            edgeOut[eb + CCH + co0 + r1] = __float2half(v11);
                        }
                        if (wid == 3 && n == 7 && tig == 3) {       // t_loc 254,255
                            size_t eb = ((size_t)(bb * 32 + ti) * 4 + 2) * CCH;
                            edgeOut[eb + co0 + r0]       = __float2half(v00);
                            edgeOut[eb + CCH + co0 + r0] = __float2half(v01);
                            edgeOut[eb + co0 + r1]       = __float2half(v10);
                            edgeOut[eb + CCH + co0 + r1] = __float2half(v11);
                        }
                    }
                }
                __syncthreads();
                // ---- phase 2: act2 on tile, transposed coalesced store ----
                {
                    int tb  = tid >> 3;            // t-block (16 t each)
                    int cig = (tid & 7) * 8;       // 8 ci rows
                    uint32_t outw[16][4];
#pragma unroll
                    for (int j = 0; j < 4; j++) {
                        int ra = cig + 2 * j;
                        uint32_t pa = ep + (uint32_t)(ra * EPIT + tb * 32);
                        uint32_t pb = pa + EPIT;
                        float fa[18], fb[18];
                        q8f(lds128(pa), fa + 1); q8f(lds128(pa + 16), fa + 9);
                        q8f(lds128(pb), fb + 1); q8f(lds128(pb + 16), fb + 9);
                        fa[0]  = h2f16(lds16u(tb ? pa - 2 : pa));
                        fb[0]  = h2f16(lds16u(tb ? pb - 2 : pb));
                        fa[17] = h2f16(lds16u(pa + 32));
                        fb[17] = h2f16(lds16u(pb + 32));
                        float aaA = a2[co0 + ra],     biA = 0.5f * binv[co0 + ra];
                        float aaB = a2[co0 + ra + 1], biB = 0.5f * binv[co0 + ra + 1];
#pragma unroll
                        for (int s = 0; s < 16; s++) {
                            float u0A = fmaf(0.25f, fa[s],     0.75f * fa[s + 1]);
                            float u1A = fmaf(0.25f, fa[s + 2], 0.75f * fa[s + 1]);
                            float u0B = fmaf(0.25f, fb[s],     0.75f * fb[s + 1]);
                            float u1B = fmaf(0.25f, fb[s + 2], 0.75f * fb[s + 1]);
                            float yA = fmaf(0.5f, u0A + u1A,
                                (2.f - __cosf(aaA * u0A) - __cosf(aaA * u1A)) * biA);
                            float yB = fmaf(0.5f, u0B + u1B,
                                (2.f - __cosf(aaB * u0B) - __cosf(aaB * u1B)) * biB);
                            __half2 hp = __floats2half2_rn(yA, yB);
                            outw[s][j] = *(uint32_t*)&hp;
                        }
                    }
                    // unconditional stores: t%256==0/255 columns are overwritten
                    // by edge_act_kernel afterwards (ordered by launch sequence)
#pragma unroll
                    for (int s = 0; s < 16; s++) {
                        int tl = tb * 16 + s;
                        __half* dst = actOut + ((size_t)bb * TT + t0 + tl) * CCH
                                      + co0 + cig;
                        *(uint4*)dst = make_uint4(outw[s][0], outw[s][1],
                                                  outw[s][2], outw[s][3]);
                    }
                }
                // ---- zero accumulators for next tile ----
#pragma unroll
                for (int m = 0; m < 4; m++)
#pragma unroll
                    for (int n = 0; n < 8; n++)
#pragma unroll
                        for (int q = 0; q < 4; q++) acc[m][n][q] = 0.f;
            } else {
                // ---- conv2 epilogue: fp32 + residual ----
#pragma unroll
                for (int m = 0; m < 4; m++) {
                    int r0 = co0 + m * 16 + gid;
                    int r1 = r0 + 8;
                    float b0 = bias[r0], b1 = bias[r1];
                    size_t o0 = ((size_t)(bb * CCH + r0)) * TT + t0;
                    size_t o1 = ((size_t)(bb * CCH + r1)) * TT + t0;
#pragma unroll
                    for (int n = 0; n < 8; n++) {
                        int tof = wid * 64 + n * 8 + 2 * tig;
                        float2 rv0 = *(const float2*)(resid + o0 + tof);
                        float2 rv1 = *(const float2*)(resid + o1 + tof);
                        *(float2*)(fOut + o0 + tof) =
                            make_float2(acc[m][n][0] + b0 + rv0.x,
                                        acc[m][n][1] + b0 + rv0.y);
                        *(float2*)(fOut + o1 + tof) =
                            make_float2(acc[m][n][2] + b1 + rv1.x,
                                        acc[m][n][3] + b1 + rv1.y);
#pragma unroll
                        for (int q = 0; q < 4; q++) acc[m][n][q] = 0.f;
                    }
                }
            }
        }
    }
}

// ---------------- kernel 4: act2 for tile-edge columns --------------------------
__global__ void edge_act_kernel(const __half* __restrict__ edge,
                                const float* __restrict__ a2,
                                const float* __restrict__ binv,
                                __half* __restrict__ actOut)
{
    int k = blockIdx.x, b = blockIdx.y;
    int ci = threadIdx.x * 2;
    float2 aa = make_float2(a2[ci], a2[ci + 1]);
    float2 bi = make_float2(0.5f * binv[ci], 0.5f * binv[ci + 1]);

    auto ld2 = [&](int kk, int e) {
        const __half2* p = (const __half2*)(edge + ((size_t)((b * 32 + kk) * 4 + e)) * CCH + ci);
        return __half22float2(*p);
    };
    auto snake = [&](float2 xm, float2 x0, float2 xp, bool first) {
        float2 u0, u1, y;
        u0.x = first ? x0.x : fmaf(0.25f, xm.x, 0.75f * x0.x);
        u0.y = first ? x0.y : fmaf(0.25f, xm.y, 0.75f * x0.y);
        u1.x = fmaf(0.25f, xp.x, 0.75f * x0.x);
        u1.y = fmaf(0.25f, xp.y, 0.75f * x0.y);
        y.x = fmaf(0.5f, u0.x + u1.x,
                   (2.f - __cosf(aa.x * u0.x) - __cosf(aa.x * u1.x)) * bi.x);
        y.y = fmaf(0.5f, u0.y + u1.y,
                   (2.f - __cosf(aa.y * u0.y) - __cosf(aa.y * u1.y)) * bi.y);
        return y;
    };

    // t = k*256  (e0; xm = prev tile e3)
    {
        float2 x0 = ld2(k, 0), xp = ld2(k, 1);
        float2 xm = (k > 0) ? ld2(k - 1, 3) : x0;
        float2 y = snake(xm, x0, xp, k == 0);
        *(__half2*)(actOut + ((size_t)b * TT + k * 256) * CCH + ci) =
            __floats2half2_rn(y.x, y.y);
    }
    // t = k*256 + 255  (e3; xp = next tile e0, clamp at global end)
    {
        float2 xm = ld2(k, 2), x0 = ld2(k, 3);
        float2 xp = (k < 31) ? ld2(k + 1, 0) : x0;
        float2 y = snake(xm, x0, xp, false);
        *(__half2*)(actOut + ((size_t)b * TT + k * 256 + 255) * CCH + ci) =
            __floats2half2_rn(y.x, y.y);
    }
}

// ---------------------------------- launch ---------------------------------------
extern "C" void kernel_launch(void* const* d_in, const int* in_sizes, int n_in,
                              void* d_out, int out_size)
{
    const float* x      = (const float*)d_in[0];
    const float* v1     = (const float*)d_in[1];
    const float* g1     = (const float*)d_in[2];
    const float* bias1  = (const float*)d_in[3];
    const float* v2     = (const float*)d_in[4];
    const float* g2     = (const float*)d_in[5];
    const float* bias2  = (const float*)d_in[6];
    const float* alpha1 = (const float*)d_in[7];
    const float* beta1  = (const float*)d_in[8];
    const float* alpha2 = (const float*)d_in[9];
    const float* beta2  = (const float*)d_in[10];
    float* out = (float*)d_out;

    __half *aA, *aB, *eg, *w1, *w2;
    float *a2c, *binv;
    cudaGetSymbolAddress((void**)&aA,   g_actT);
    cudaGetSymbolAddress((void**)&aB,   g_actT2);
    cudaGetSymbolAddress((void**)&eg,   g_edge);
    cudaGetSymbolAddress((void**)&w1,   g_w1);
    cudaGetSymbolAddress((void**)&w2,   g_w2);
    cudaGetSymbolAddress((void**)&a2c,  g_a2c);
    cudaGetSymbolAddress((void**)&binv, g_binv);

    static bool attr_set = false;
    if (!attr_set) {
        cudaFuncSetAttribute(conv_mma_kernel<true>,
                             cudaFuncAttributeMaxDynamicSharedMemorySize, SM_TOTAL);
        cudaFuncSetAttribute(conv_mma_kernel<false>,
                             cudaFuncAttributeMaxDynamicSharedMemorySize, SM_TOTAL);
        attr_set = true;
    }

    dim3 wgrid(CCH, 2);
    wnorm_kernel<<<wgrid, 256>>>(v1, g1, alpha1, beta1,
                                 v2, g2, alpha2, beta2,
                                 w1, w2, a2c, binv);

    dim3 agrid(TT / ATT, CCH / ATI, BSZ);
    snake_actT_kernel<<<agrid, 256>>>(x, a2c, binv, aA);

    // conv1 (+fused act2 interior) -> actT2 ; edge cols -> g_edge
    conv_mma_kernel<true><<<GRID, CTN, SM_TOTAL>>>(
        aA, w1, bias1, nullptr, a2c + CCH, binv + CCH, aB, eg, nullptr);

    // act2 edge columns (overwrites t%256==0/255 of actT2)
    edge_act_kernel<<<dim3(32, BSZ), 256>>>(eg, a2c + CCH, binv + CCH, aB);

    // conv2 + residual -> out
    conv_mma_kernel<false><<<GRID, CTN, SM_TOTAL>>>(
        aB, w2, bias2, x, nullptr, nullptr, nullptr, nullptr, out);
}

// round 16
// speedup vs baseline: 1.2324x; 1.0847x over previous
#include <cuda_runtime.h>
#include <cuda_fp16.h>
#include <math.h>
#include <stdint.h>

#define BSZ 8
#define CCH 512
#define TT  8192
#define NEL (BSZ*CCH*TT)
#define KW  3

// ---- conv tiling: tile = 64 co x 256 t, 4 warps, 3-stage ring, persistent ----
#define MCO 64
#define NTT 256
#define CC  32
#define NCHUNK (CCH/CC)               // 16 chunks per tile
#define ROWB 80
#define A_TILE (64*ROWB)              // 5120
#define BROWS 264
#define B_TILE (BROWS*ROWB)           // 21120
#define SM_BOFF (3*A_TILE)            // 15360
#define STAGE (3*A_TILE + B_TILE)     // 36480
#define NSTAGE 3
#define SM_TOTAL (NSTAGE*STAGE)       // 109440 (2 CTA/SM)
#define CTN 128
#define GRID 296                      // persistent CTAs (2 x 148)
#define NTILE (BSZ*(CCH/MCO)*(TT/NTT))// 2048
#define EPIT 544                      // epilogue c1 tile row pitch (bytes, 16B-aligned)
#define NSEG 1824                     // cp.async segs per chunk (768 W + 1056 B)
#define SEGP 608                      // segs per issue part (NSEG/3)

// ---------------- scratch ------------------------------------------------------
__device__ __half g_actT[NEL];            // act1 out  [b][t][ci] fp16 (conv1 input)
__device__ __half g_actT2[NEL];           // act2 out  [b][t][ci] fp16 (conv2 input)
__device__ __half g_edge[BSZ*32*4*CCH];   // c1 edge cols [b][k][e][co], e:{0,1,254,255}
__device__ __half g_w1[3*CCH*CCH];        // [tap][co][ci] fp16
__device__ __half g_w2[3*CCH*CCH];
__device__ float  g_a2c[2*CCH];           // 2*exp(alpha)
__device__ float  g_binv[2*CCH];          // 1/(2exp(beta)+eps)

// ---------------- PTX helpers ---------------------------------------------------
__device__ __forceinline__ void cp16(uint32_t dst, const void* src, bool pred) {
    asm volatile("cp.async.ca.shared.global [%0], [%1], 16, %2;"
                 :: "r"(dst), "l"(src), "r"(pred ? 16 : 0));
}
__device__ __forceinline__ void cp_commit() { asm volatile("cp.async.commit_group;"); }
template<int N> __device__ __forceinline__ void cp_wait() {
    asm volatile("cp.async.wait_group %0;" :: "n"(N));
}
__device__ __forceinline__ void ldx4(uint32_t* r, uint32_t addr) {
    asm volatile("ldmatrix.sync.aligned.m8n8.x4.shared.b16 {%0,%1,%2,%3}, [%4];"
                 : "=r"(r[0]), "=r"(r[1]), "=r"(r[2]), "=r"(r[3]) : "r"(addr));
}
__device__ __forceinline__ void mma16816(float* d, const uint32_t* a, const uint32_t* b) {
    asm volatile(
        "mma.sync.aligned.m16n8k16.row.col.f32.f16.f16.f32 "
        "{%0,%1,%2,%3}, {%4,%5,%6,%7}, {%8,%9}, {%0,%1,%2,%3};"
        : "+f"(d[0]), "+f"(d[1]), "+f"(d[2]), "+f"(d[3])
        : "r"(a[0]), "r"(a[1]), "r"(a[2]), "r"(a[3]), "r"(b[0]), "r"(b[1]));
}
__device__ __forceinline__ void sts32(uint32_t addr, uint32_t v) {
    asm volatile("st.shared.b32 [%0], %1;" :: "r"(addr), "r"(v) : "memory");
}
__device__ __forceinline__ uint4 lds128(uint32_t addr) {
    uint4 q;
    asm volatile("ld.shared.v4.b32 {%0,%1,%2,%3}, [%4];"
                 : "=r"(q.x), "=r"(q.y), "=r"(q.z), "=r"(q.w) : "r"(addr));
    return q;
}
__device__ __forceinline__ uint32_t lds16u(uint32_t addr) {
    uint32_t v;
    asm volatile("ld.shared.u16 %0, [%1];" : "=r"(v) : "r"(addr));
    return v;
}
__device__ __forceinline__ float h2f16(uint32_t u) {
    __half_raw r; r.x = (unsigned short)u;
    return __half2float((__half)r);
}
__device__ __forceinline__ void q8f(uint4 q, float* f) {
    float2 t;
    t = __half22float2(*(const __half2*)&q.x); f[0] = t.x; f[1] = t.y;
    t = __half22float2(*(const __half2*)&q.y); f[2] = t.x; f[3] = t.y;
    t = __half22float2(*(const __half2*)&q.z); f[4] = t.x; f[5] = t.y;
    t = __half22float2(*(const __half2*)&q.w); f[6] = t.x; f[7] = t.y;
}

// ---------------- kernel 1: weight norm (both convs) -> fp16 [tap][co][ci] ------
__global__ void wnorm_kernel(const float* __restrict__ v1, const float* __restrict__ g1,
                             const float* __restrict__ al1, const float* __restrict__ be1,
                             const float* __restrict__ v2, const float* __restrict__ g2,
                             const float* __restrict__ al2, const float* __restrict__ be2,
                             __half* __restrict__ w1o, __half* __restrict__ w2o,
                             float* __restrict__ a2out, float* __restrict__ binvout)
{
    int set = blockIdx.y;
    const float* v     = set ? v2 : v1;
    const float* g     = set ? g2 : g1;
    const float* alpha = set ? al2 : al1;
    const float* beta  = set ? be2 : be1;
    __half* wsp        = set ? w2o : w1o;
    int co = blockIdx.x;
    const float* vc = v + co * (CCH * KW);
    float s = 0.f;
    for (int i = threadIdx.x; i < CCH * KW; i += 256) { float t = vc[i]; s += t * t; }
    __shared__ float red[256];
    red[threadIdx.x] = s;
    __syncthreads();
    for (int off = 128; off > 0; off >>= 1) {
        if (threadIdx.x < off) red[threadIdx.x] += red[threadIdx.x + off];
        __syncthreads();
    }
    float scale = g[co] / sqrtf(red[0]);
    for (int i = threadIdx.x; i < CCH * KW; i += 256) {
        int ci = i / KW, k = i % KW;
        wsp[((size_t)k * CCH + co) * CCH + ci] = __float2half(vc[i] * scale);
    }
    if (threadIdx.x == 0) {
        a2out[set * CCH + co]   = 2.f * expf(alpha[co]);
        binvout[set * CCH + co] = 1.f / (2.f * expf(beta[co]) + 1e-9f);
    }
}

// ---------------- kernel 2: SnakeBeta act1 (x fp32 -> actT fp16) ----------------
#define ATI 64
#define ATT 64
__global__ __launch_bounds__(256)
void snake_actT_kernel(const float* __restrict__ in,
                       const float* __restrict__ a2,
                       const float* __restrict__ binv,
                       __half* __restrict__ oA)
{
    __shared__ float xs[ATI][ATT + 3];
    int tid = threadIdx.x;
    int b = blockIdx.z, ci0 = blockIdx.y * ATI, t0 = blockIdx.x * ATT;
    const float* xb = in + ((size_t)b * CCH + ci0) * TT;

    // division-free staging: warp covers 4 rows x 8 cols (full 32B sectors)
    {
        int rr = tid >> 3;          // 0..31
        int cc = tid & 7;
#pragma unroll
        for (int rb = 0; rb < ATI; rb += 32) {
            int r = rb + rr;
            const float* row = xb + r * TT;
#pragma unroll
            for (int c = cc; c < ATT + 2; c += 8) {
                int t = t0 - 1 + c;
                float v;
                if (t < 0)        v = 0.f;
                else if (t >= TT) v = row[TT - 1];
                else              v = row[t];
                xs[r][c] = v;
            }
        }
    }
    __syncthreads();

    int w = tid >> 5, l = tid & 31;
    int ciA = 2 * l, ciB = 2 * l + 1;
    float aaA = a2[ci0 + ciA], biA = 0.5f * binv[ci0 + ciA];
    float aaB = a2[ci0 + ciB], biB = 0.5f * binv[ci0 + ciB];

    const float* pA = &xs[ciA][w * 8];
    const float* pB = &xs[ciB][w * 8];
    float xmA = pA[0], x0A = pA[1];
    float xmB = pB[0], x0B = pB[1];

    __half* op = oA + ((size_t)b * TT + t0 + w * 8) * CCH + ci0 + ciA;
    int tfirst = t0 + w * 8;

#pragma unroll
    for (int s = 0; s < 8; s++) {
        float xpA = pA[s + 2];
        float xpB = pB[s + 2];
        float u0A = fmaf(0.25f, xmA, 0.75f * x0A);
        float u0B = fmaf(0.25f, xmB, 0.75f * x0B);
        if (tfirst + s == 0) { u0A = x0A; u0B = x0B; }
        float u1A = fmaf(0.25f, xpA, 0.75f * x0A);
        float u1B = fmaf(0.25f, xpB, 0.75f * x0B);
        float cA = 2.f - __cosf(aaA * u0A) - __cosf(aaA * u1A);
        float cB = 2.f - __cosf(aaB * u0B) - __cosf(aaB * u1B);
        float yA = fmaf(0.5f, u0A + u1A, cA * biA);
        float yB = fmaf(0.5f, u0B + u1B, cB * biB);
        *(__half2*)op = __floats2half2_rn(yA, yB);
        op += CCH;
        xmA = x0A; x0A = xpA;
        xmB = x0B; x0B = xpB;
    }
}

// ---------------- kernel 3: persistent conv via mma.sync fp16 -------------------
// FUSE=true : conv1 — epilogue applies SnakeBeta act2 in-smem and writes
//             actOut [b][t][ci] fp16 directly; edge cols via edgeOut + edge kernel.
// FUSE=false: conv2 — fp32 + residual to fOut.
// cp.async issue for chunk G+2 is split into 3 parts interleaved with the ks=0
// tap groups' MMAs, so the issue burst rides in MMA shadow instead of stalling
// the tensor pipe right after the barrier.
template<bool FUSE>
__global__ __launch_bounds__(CTN, 2)
void conv_mma_kernel(const __half* __restrict__ aA,
                     const __half* __restrict__ Wsp,
                     const float* __restrict__ bias,
                     const float* __restrict__ resid,
                     const float* __restrict__ a2,
                     const float* __restrict__ binv,
                     __half* __restrict__ actOut,
                     __half* __restrict__ edgeOut,
                     float* __restrict__ fOut)
{
    extern __shared__ char smem[];
    const uint32_t sbase = (uint32_t)__cvta_generic_to_shared(smem);
    const int tid  = threadIdx.x;
    const int wid  = tid >> 5, lane = tid & 31;
    const int gid  = lane >> 2, tig = lane & 3;
    const int bid  = blockIdx.x;

    const int nt = (bid < NTILE) ? ((NTILE - 1 - bid) / GRID + 1) : 0;
    const int nG = nt * NCHUNK;

    float acc[4][8][4];
#pragma unroll
    for (int m = 0; m < 4; m++)
#pragma unroll
        for (int n = 0; n < 8; n++)
#pragma unroll
            for (int q = 0; q < 4; q++) acc[m][n][q] = 0.f;

    // issue one third of chunk G's cp.asyncs (part 0..2); commit in part 2.
    auto issuePart = [&](int G, int part) {
        int tau = bid + (G >> 4) * GRID;
        if (tau < NTILE) {
            int ch  = G & 15;
            int ti  = tau & 31;
            int cog = (tau >> 5) & 7;
            int bb  = tau >> 8;
            int co0 = cog * MCO;
            int t0  = ti * NTT;
            int ci0 = ch * CC;
            const __half* aBase = aA + (size_t)bb * TT * CCH;
            const uint32_t sb = sbase + (uint32_t)(G % NSTAGE) * STAGE;
            int uend = (part + 1) * SEGP;
            for (int u = part * SEGP + tid; u < uend; u += CTN) {
                if (u < 768) {
                    int tile = u >> 8;
                    int rem  = u & 255;
                    int row  = rem >> 2;
                    int seg  = rem & 3;
                    const __half* src =
                        Wsp + ((size_t)(tile * CCH + co0 + row)) * CCH + ci0 + seg * 8;
                    cp16(sb + tile * A_TILE + row * ROWB + seg * 16, src, true);
                } else {
                    int u2  = u - 768;
                    int row = u2 >> 2;
                    int seg = u2 & 3;
                    int t   = t0 - 1 + row;
                    bool ok = (t >= 0 && t < TT && row < NTT + 2);
                    int tc  = ok ? t : 0;
                    const __half* src = aBase + (size_t)tc * CCH + ci0 + seg * 8;
                    cp16(sb + SM_BOFF + row * ROWB + seg * 16, src, ok);
                }
            }
        }
        if (part == 2) cp_commit();
    };
    auto issueAll = [&](int G) {
        issuePart(G, 0); issuePart(G, 1); issuePart(G, 2);
    };

    issueAll(0);
    issueAll(1);

    const uint32_t aoffb = (uint32_t)((lane & 15) * ROWB + (lane >> 4) * 16);
    const uint32_t boffb = (uint32_t)(((lane & 7) + ((lane >> 4) << 3) + wid * 64) * ROWB
                                      + ((lane >> 3) & 1) * 16);

    for (int G = 0; G < nG; G++) {
        cp_wait<1>();
        __syncthreads();

        const uint32_t sb = sbase + (uint32_t)(G % NSTAGE) * STAGE;
        const uint32_t abase = sb + aoffb;
        const uint32_t bbase = sb + SM_BOFF + boffb;
#pragma unroll
        for (int ks = 0; ks < 2; ks++) {
#pragma unroll
            for (int tap = 0; tap < 3; tap++) {
                uint32_t bq[4][4];
#pragma unroll
                for (int np = 0; np < 4; np++)
                    ldx4(bq[np], bbase + (uint32_t)((np * 16 + tap) * ROWB + ks * 32));
#pragma unroll
                for (int m = 0; m < 4; m++) {
                    uint32_t af[4];
                    ldx4(af, abase + (uint32_t)(tap * A_TILE + m * 16 * ROWB + ks * 32));
#pragma unroll
                    for (int np = 0; np < 4; np++) {
                        mma16816(acc[m][2 * np],     af, &bq[np][0]);
                        mma16816(acc[m][2 * np + 1], af, &bq[np][2]);
                    }
                }
                if (ks == 0) issuePart(G + 2, tap);   // interleaved issue thirds
            }
        }

        if ((G & 15) == 15) {
            int tau = bid + (G >> 4) * GRID;
            int ti  = tau & 31;
            int cog = (tau >> 5) & 7;
            int bb  = tau >> 8;
            int co0 = cog * MCO;
            int t0  = ti * NTT;

            if (FUSE) {
                // ---- phase 0: all warps done reading stage G ----
                __syncthreads();
                const uint32_t ep = sbase + (uint32_t)(G % NSTAGE) * STAGE;
                // ---- phase 1: STS c1 tile fp16 [co][t] + edge column dump ----
#pragma unroll
                for (int m = 0; m < 4; m++) {
                    int r0 = m * 16 + gid, r1 = r0 + 8;
                    float b0 = bias[co0 + r0], b1 = bias[co0 + r1];
#pragma unroll
                    for (int n = 0; n < 8; n++) {
                        int tl = wid * 64 + n * 8 + 2 * tig;
                        float v00 = acc[m][n][0] + b0, v01 = acc[m][n][1] + b0;
                        float v10 = acc[m][n][2] + b1, v11 = acc[m][n][3] + b1;
                        __half2 h0 = __floats2half2_rn(v00, v01);
                        __half2 h1 = __floats2half2_rn(v10, v11);
                        sts32(ep + (uint32_t)(r0 * EPIT + tl * 2), *(uint32_t*)&h0);
                        sts32(ep + (uint32_t)(r1 * EPIT + tl * 2), *(uint32_t*)&h1);
                        if (wid == 0 && n == 0 && tig == 0) {       // t_loc 0,1
                            size_t eb = ((size_t)(bb * 32 + ti) * 4) * CCH;
                            edgeOut[eb + co0 + r0]       = __float2half(v00);
                            edgeOut[eb + CCH + co0 + r0] = __float2half(v01);
                            edgeOut[eb + co0 + r1]       = __float2half(v10);
                            edgeOut[eb + CCH + co0 + r1] = __float2half(v11);
                        }
                        if (wid == 3 && n == 7 && tig == 3) {       // t_loc 254,255
                            size_t eb = ((size_t)(bb * 32 + ti) * 4 + 2) * CCH;
                            edgeOut[eb + co0 + r0]       = __float2half(v00);
                            edgeOut[eb + CCH + co0 + r0] = __float2half(v01);
                            edgeOut[eb + co0 + r1]       = __float2half(v10);
                            edgeOut[eb + CCH + co0 + r1] = __float2half(v11);
                        }
                    }
                }
                __syncthreads();
                // ---- phase 2: act2 on tile, transposed coalesced store ----
                {
                    int tb  = tid >> 3;            // t-block (16 t each)
                    int cig = (tid & 7) * 8;       // 8 ci rows
                    uint32_t outw[16][4];
#pragma unroll
                    for (int j = 0; j < 4; j++) {
                        int ra = cig + 2 * j;
                        uint32_t pa = ep + (uint32_t)(ra * EPIT + tb * 32);
                        uint32_t pb = pa + EPIT;
                        float fa[18], fb[18];
                        q8f(lds128(pa), fa + 1); q8f(lds128(pa + 16), fa + 9);
                        q8f(lds128(pb), fb + 1); q8f(lds128(pb + 16), fb + 9);
                        fa[0]  = h2f16(lds16u(tb ? pa - 2 : pa));
                        fb[0]  = h2f16(lds16u(tb ? pb - 2 : pb));
                        fa[17] = h2f16(lds16u(pa + 32));
                        fb[17] = h2f16(lds16u(pb + 32));
                        float aaA = a2[co0 + ra],     biA = 0.5f * binv[co0 + ra];
                        float aaB = a2[co0 + ra + 1], biB = 0.5f * binv[co0 + ra + 1];
#pragma unroll
                        for (int s = 0; s < 16; s++) {
                            float u0A = fmaf(0.25f, fa[s],     0.75f * fa[s + 1]);
                            float u1A = fmaf(0.25f, fa[s + 2], 0.75f * fa[s + 1]);
                            float u0B = fmaf(0.25f, fb[s],     0.75f * fb[s + 1]);
                            float u1B = fmaf(0.25f, fb[s + 2], 0.75f * fb[s + 1]);
                            float yA = fmaf(0.5f, u0A + u1A,
                                (2.f - __cosf(aaA * u0A) - __cosf(aaA * u1A)) * biA);
                            float yB = fmaf(0.5f, u0B + u1B,
                                (2.f - __cosf(aaB * u0B) - __cosf(aaB * u1B)) * biB);
                            __half2 hp = __floats2half2_rn(yA, yB);
                            outw[s][j] = *(uint32_t*)&hp;
                        }
                    }
                    // unconditional stores: t%256==0/255 overwritten by edge kernel
#pragma unroll
                    for (int s = 0; s < 16; s++) {
                        int tl = tb * 16 + s;
                        __half* dst = actOut + ((size_t)bb * TT + t0 + tl) * CCH
                                      + co0 + cig;
                        *(uint4*)dst = make_uint4(outw[s][0], outw[s][1],
                                                  outw[s][2], outw[s][3]);
                    }
                }
                // ---- zero accumulators for next tile ----
#pragma unroll
                for (int m = 0; m < 4; m++)
#pragma unroll
                    for (int n = 0; n < 8; n++)
#pragma unroll
                        for (int q = 0; q < 4; q++) acc[m][n][q] = 0.f;
            } else {
                // ---- conv2 epilogue: fp32 + residual ----
#pragma unroll
                for (int m = 0; m < 4; m++) {
                    int r0 = co0 + m * 16 + gid;
                    int r1 = r0 + 8;
                    float b0 = bias[r0], b1 = bias[r1];
                    size_t o0 = ((size_t)(bb * CCH + r0)) * TT + t0;
                    size_t o1 = ((size_t)(bb * CCH + r1)) * TT + t0;
#pragma unroll
                    for (int n = 0; n < 8; n++) {
                        int tof = wid * 64 + n * 8 + 2 * tig;
                        float2 rv0 = *(const float2*)(resid + o0 + tof);
                        float2 rv1 = *(const float2*)(resid + o1 + tof);
                        *(float2*)(fOut + o0 + tof) =
                            make_float2(acc[m][n][0] + b0 + rv0.x,
                                        acc[m][n][1] + b0 + rv0.y);
                        *(float2*)(fOut + o1 + tof) =
                            make_float2(acc[m][n][2] + b1 + rv1.x,
                                        acc[m][n][3] + b1 + rv1.y);
#pragma unroll
                        for (int q = 0; q < 4; q++) acc[m][n][q] = 0.f;
                    }
                }
            }
        }
    }
}

// ---------------- kernel 4: act2 for tile-edge columns --------------------------
__global__ void edge_act_kernel(const __half* __restrict__ edge,
                                const float* __restrict__ a2,
                                const float* __restrict__ binv,
                                __half* __restrict__ actOut)
{
    int k = blockIdx.x, b = blockIdx.y;
    int ci = threadIdx.x * 2;
    float2 aa = make_float2(a2[ci], a2[ci + 1]);
    float2 bi = make_float2(0.5f * binv[ci], 0.5f * binv[ci + 1]);

    auto ld2 = [&](int kk, int e) {
        const __half2* p = (const __half2*)(edge + ((size_t)((b * 32 + kk) * 4 + e)) * CCH + ci);
        return __half22float2(*p);
    };
    auto snake = [&](float2 xm, float2 x0, float2 xp, bool first) {
        float2 u0, u1, y;
        u0.x = first ? x0.x : fmaf(0.25f, xm.x, 0.75f * x0.x);
        u0.y = first ? x0.y : fmaf(0.25f, xm.y, 0.75f * x0.y);
        u1.x = fmaf(0.25f, xp.x, 0.75f * x0.x);
        u1.y = fmaf(0.25f, xp.y, 0.75f * x0.y);
        y.x = fmaf(0.5f, u0.x + u1.x,
                   (2.f - __cosf(aa.x * u0.x) - __cosf(aa.x * u1.x)) * bi.x);
        y.y = fmaf(0.5f, u0.y + u1.y,
                   (2.f - __cosf(aa.y * u0.y) - __cosf(aa.y * u1.y)) * bi.y);
        return y;
    };

    // t = k*256  (e0; xm = prev tile e3)
    {
        float2 x0 = ld2(k, 0), xp = ld2(k, 1);
        float2 xm = (k > 0) ? ld2(k - 1, 3) : x0;
        float2 y = snake(xm, x0, xp, k == 0);
        *(__half2*)(actOut + ((size_t)b * TT + k * 256) * CCH + ci) =
            __floats2half2_rn(y.x, y.y);
    }
    // t = k*256 + 255  (e3; xp = next tile e0, clamp at global end)
    {
        float2 xm = ld2(k, 2), x0 = ld2(k, 3);
        float2 xp = (k < 31) ? ld2(k + 1, 0) : x0;
        float2 y = snake(xm, x0, xp, false);
        *(__half2*)(actOut + ((size_t)b * TT + k * 256 + 255) * CCH + ci) =
            __floats2half2_rn(y.x, y.y);
    }
}

// ---------------------------------- launch ---------------------------------------
extern "C" void kernel_launch(void* const* d_in, const int* in_sizes, int n_in,
                              void* d_out, int out_size)
{
    const float* x      = (const float*)d_in[0];
    const float* v1     = (const float*)d_in[1];
    const float* g1     = (const float*)d_in[2];
    const float* bias1  = (const float*)d_in[3];
    const float* v2     = (const float*)d_in[4];
    const float* g2     = (const float*)d_in[5];
    const float* bias2  = (const float*)d_in[6];
    const float* alpha1 = (const float*)d_in[7];
    const float* beta1  = (const float*)d_in[8];
    const float* alpha2 = (const float*)d_in[9];
    const float* beta2  = (const float*)d_in[10];
    float* out = (float*)d_out;

    __half *aA, *aB, *eg, *w1, *w2;
    float *a2c, *binv;
    cudaGetSymbolAddress((void**)&aA,   g_actT);
    cudaGetSymbolAddress((void**)&aB,   g_actT2);
    cudaGetSymbolAddress((void**)&eg,   g_edge);
    cudaGetSymbolAddress((void**)&w1,   g_w1);
    cudaGetSymbolAddress((void**)&w2,   g_w2);
    cudaGetSymbolAddress((void**)&a2c,  g_a2c);
    cudaGetSymbolAddress((void**)&binv, g_binv);

    static bool attr_set = false;
    if (!attr_set) {
        cudaFuncSetAttribute(conv_mma_kernel<true>,
                             cudaFuncAttributeMaxDynamicSharedMemorySize, SM_TOTAL);
        cudaFuncSetAttribute(conv_mma_kernel<false>,
                             cudaFuncAttributeMaxDynamicSharedMemorySize, SM_TOTAL);
        attr_set = true;
    }

    dim3 wgrid(CCH, 2);
    wnorm_kernel<<<wgrid, 256>>>(v1, g1, alpha1, beta1,
                                 v2, g2, alpha2, beta2,
                                 w1, w2, a2c, binv);

    dim3 agrid(TT / ATT, CCH / ATI, BSZ);
    snake_actT_kernel<<<agrid, 256>>>(x, a2c, binv, aA);

    // conv1 (+fused act2 interior) -> actT2 ; edge cols -> g_edge
    conv_mma_kernel<true><<<GRID, CTN, SM_TOTAL>>>(
        aA, w1, bias1, nullptr, a2c + CCH, binv + CCH, aB, eg, nullptr);

    // act2 edge columns (overwrites t%256==0/255 of actT2)
    edge_act_kernel<<<dim3(32, BSZ), 256>>>(eg, a2c + CCH, binv + CCH, aB);

    // conv2 + residual -> out
    conv_mma_kernel<false><<<GRID, CTN, SM_TOTAL>>>(
        aB, w2, bias2, x, nullptr, nullptr, nullptr, nullptr, out);
}

// round 17
// speedup vs baseline: 1.2983x; 1.0535x over previous
#include <cuda_runtime.h>
#include <cuda_fp16.h>
#include <math.h>
#include <stdint.h>

#define BSZ 8
#define CCH 512
#define TT  8192
#define NEL (BSZ*CCH*TT)
#define KW  3

// ---- conv tiling: tile = 64 co x 256 t, 4 warps, 3-stage ring, persistent ----
#define MCO 64
#define NTT 256
#define CC  32
#define NCHUNK (CCH/CC)               // 16 chunks per tile
#define ROWB 80
#define A_TILE (64*ROWB)              // 5120
#define BROWS 264
#define B_TILE (BROWS*ROWB)           // 21120
#define SM_BOFF (3*A_TILE)            // 15360
#define STAGE (3*A_TILE + B_TILE)     // 36480
#define NSTAGE 3
#define SM_TOTAL (NSTAGE*STAGE)       // 109440 (2 CTA/SM)
#define CTN 128
#define GRID 296                      // persistent CTAs (2 x 148)
#define NTILE (BSZ*(CCH/MCO)*(TT/NTT))// 2048
#define EPIT 544                      // epilogue c1 tile row pitch (bytes, 16B-aligned)
#define NSEG 1824                     // cp.async segs per chunk (768 W + 1056 B)
#define SEGP 304                      // segs per issue part (NSEG/6)

// ---------------- scratch ------------------------------------------------------
__device__ __half g_actT[NEL];            // act1 out  [b][t][ci] fp16 (conv1 input)
__device__ __half g_actT2[NEL];           // act2 out  [b][t][ci] fp16 (conv2 input)
__device__ __half g_edge[BSZ*32*4*CCH];   // c1 edge cols [b][k][e][co], e:{0,1,254,255}
__device__ __half g_w1[3*CCH*CCH];        // [tap][co][ci] fp16
__device__ __half g_w2[3*CCH*CCH];
__device__ float  g_a2c[2*CCH];           // 2*exp(alpha)
__device__ float  g_binv[2*CCH];          // 1/(2exp(beta)+eps)

// ---------------- PTX helpers ---------------------------------------------------
__device__ __forceinline__ void cp16(uint32_t dst, const void* src, bool pred) {
    asm volatile("cp.async.ca.shared.global [%0], [%1], 16, %2;"
                 :: "r"(dst), "l"(src), "r"(pred ? 16 : 0));
}
__device__ __forceinline__ void cp_commit() { asm volatile("cp.async.commit_group;"); }
template<int N> __device__ __forceinline__ void cp_wait() {
    asm volatile("cp.async.wait_group %0;" :: "n"(N));
}
__device__ __forceinline__ void ldx4(uint32_t* r, uint32_t addr) {
    asm volatile("ldmatrix.sync.aligned.m8n8.x4.shared.b16 {%0,%1,%2,%3}, [%4];"
                 : "=r"(r[0]), "=r"(r[1]), "=r"(r[2]), "=r"(r[3]) : "r"(addr));
}
__device__ __forceinline__ void mma16816(float* d, const uint32_t* a, const uint32_t* b) {
    asm volatile(
        "mma.sync.aligned.m16n8k16.row.col.f32.f16.f16.f32 "
        "{%0,%1,%2,%3}, {%4,%5,%6,%7}, {%8,%9}, {%0,%1,%2,%3};"
        : "+f"(d[0]), "+f"(d[1]), "+f"(d[2]), "+f"(d[3])
        : "r"(a[0]), "r"(a[1]), "r"(a[2]), "r"(a[3]), "r"(b[0]), "r"(b[1]));
}
__device__ __forceinline__ void sts32(uint32_t addr, uint32_t v) {
    asm volatile("st.shared.b32 [%0], %1;" :: "r"(addr), "r"(v) : "memory");
}
__device__ __forceinline__ uint4 lds128(uint32_t addr) {
    uint4 q;
    asm volatile("ld.shared.v4.b32 {%0,%1,%2,%3}, [%4];"
                 : "=r"(q.x), "=r"(q.y), "=r"(q.z), "=r"(q.w) : "r"(addr));
    return q;
}
__device__ __forceinline__ uint32_t lds16u(uint32_t addr) {
    uint32_t v;
    asm volatile("ld.shared.u16 %0, [%1];" : "=r"(v) : "r"(addr));
    return v;
}
__device__ __forceinline__ float h2f16(uint32_t u) {
    __half_raw r; r.x = (unsigned short)u;
    return __half2float((__half)r);
}
__device__ __forceinline__ void q8f(uint4 q, float* f) {
    float2 t;
    t = __half22float2(*(const __half2*)&q.x); f[0] = t.x; f[1] = t.y;
    t = __half22float2(*(const __half2*)&q.y); f[2] = t.x; f[3] = t.y;
    t = __half22float2(*(const __half2*)&q.z); f[4] = t.x; f[5] = t.y;
    t = __half22float2(*(const __half2*)&q.w); f[6] = t.x; f[7] = t.y;
}

// ---------------- kernel 1: weight norm (both convs) -> fp16 [tap][co][ci] ------
__global__ void wnorm_kernel(const float* __restrict__ v1, const float* __restrict__ g1,
                             const float* __restrict__ al1, const float* __restrict__ be1,
                             const float* __restrict__ v2, const float* __restrict__ g2,
                             const float* __restrict__ al2, const float* __restrict__ be2,
                             __half* __restrict__ w1o, __half* __restrict__ w2o,
                             float* __restrict__ a2out, float* __restrict__ binvout)
{
    int set = blockIdx.y;
    const float* v     = set ? v2 : v1;
    const float* g     = set ? g2 : g1;
    const float* alpha = set ? al2 : al1;
    const float* beta  = set ? be2 : be1;
    __half* wsp        = set ? w2o : w1o;
    int co = blockIdx.x;
    const float* vc = v + co * (CCH * KW);
    float s = 0.f;
    for (int i = threadIdx.x; i < CCH * KW; i += 256) { float t = vc[i]; s += t * t; }
    __shared__ float red[256];
    red[threadIdx.x] = s;
    __syncthreads();
    for (int off = 128; off > 0; off >>= 1) {
        if (threadIdx.x < off) red[threadIdx.x] += red[threadIdx.x + off];
        __syncthreads();
    }
    float scale = g[co] / sqrtf(red[0]);
    for (int i = threadIdx.x; i < CCH * KW; i += 256) {
        int ci = i / KW, k = i % KW;
        wsp[((size_t)k * CCH + co) * CCH + ci] = __float2half(vc[i] * scale);
    }
    if (threadIdx.x == 0) {
        a2out[set * CCH + co]   = 2.f * expf(alpha[co]);
        binvout[set * CCH + co] = 1.f / (2.f * expf(beta[co]) + 1e-9f);
    }
}

// ---------------- kernel 2: SnakeBeta act1 (x fp32 -> actT fp16) ----------------
#define ATI 64
#define ATT 64
__global__ __launch_bounds__(256)
void snake_actT_kernel(const float* __restrict__ in,
                       const float* __restrict__ a2,
                       const float* __restrict__ binv,
                       __half* __restrict__ oA)
{
    __shared__ float xs[ATI][ATT + 3];
    int tid = threadIdx.x;
    int b = blockIdx.z, ci0 = blockIdx.y * ATI, t0 = blockIdx.x * ATT;
    const float* xb = in + ((size_t)b * CCH + ci0) * TT;

    // division-free staging: warp covers 4 rows x 8 cols (full 32B sectors)
    {
        int rr = tid >> 3;          // 0..31
        int cc = tid & 7;
#pragma unroll
        for (int rb = 0; rb < ATI; rb += 32) {
            int r = rb + rr;
            const float* row = xb + r * TT;
#pragma unroll
            for (int c = cc; c < ATT + 2; c += 8) {
                int t = t0 - 1 + c;
                float v;
                if (t < 0)        v = 0.f;
                else if (t >= TT) v = row[TT - 1];
                else              v = row[t];
                xs[r][c] = v;
            }
        }
    }
    __syncthreads();

    int w = tid >> 5, l = tid & 31;
    int ciA = 2 * l, ciB = 2 * l + 1;
    float aaA = a2[ci0 + ciA], biA = 0.5f * binv[ci0 + ciA];
    float aaB = a2[ci0 + ciB], biB = 0.5f * binv[ci0 + ciB];

    const float* pA = &xs[ciA][w * 8];
    const float* pB = &xs[ciB][w * 8];
    float xmA = pA[0], x0A = pA[1];
    float xmB = pB[0], x0B = pB[1];

    __half* op = oA + ((size_t)b * TT + t0 + w * 8) * CCH + ci0 + ciA;
    int tfirst = t0 + w * 8;

#pragma unroll
    for (int s = 0; s < 8; s++) {
        float xpA = pA[s + 2];
        float xpB = pB[s + 2];
        float u0A = fmaf(0.25f, xmA, 0.75f * x0A);
        float u0B = fmaf(0.25f, xmB, 0.75f * x0B);
        if (tfirst + s == 0) { u0A = x0A; u0B = x0B; }
        float u1A = fmaf(0.25f, xpA, 0.75f * x0A);
        float u1B = fmaf(0.25f, xpB, 0.75f * x0B);
        float cA = 2.f - __cosf(aaA * u0A) - __cosf(aaA * u1A);
        float cB = 2.f - __cosf(aaB * u0B) - __cosf(aaB * u1B);
        float yA = fmaf(0.5f, u0A + u1A, cA * biA);
        float yB = fmaf(0.5f, u0B + u1B, cB * biB);
        *(__half2*)op = __floats2half2_rn(yA, yB);
        op += CCH;
        xmA = x0A; x0A = xpA;
        xmB = x0B; x0B = xpB;
    }
}

// ---------------- kernel 3: persistent conv via mma.sync fp16 -------------------
// FUSE=true : conv1 — epilogue applies SnakeBeta act2 in-smem and writes
//             actOut [b][t][ci] fp16 directly; edge cols via edgeOut + edge kernel.
// FUSE=false: conv2 — fp32 + residual to fOut.
// cp.async issue for chunk G+2 is split into 6 parts, one per (ks, tap) group,
// so issue instructions ride uniformly in MMA shadow across the whole chunk.
template<bool FUSE>
__global__ __launch_bounds__(CTN, 2)
void conv_mma_kernel(const __half* __restrict__ aA,
                     const __half* __restrict__ Wsp,
                     const float* __restrict__ bias,
                     const float* __restrict__ resid,
                     const float* __restrict__ a2,
                     const float* __restrict__ binv,
                     __half* __restrict__ actOut,
                     __half* __restrict__ edgeOut,
                     float* __restrict__ fOut)
{
    extern __shared__ char smem[];
    const uint32_t sbase = (uint32_t)__cvta_generic_to_shared(smem);
    const int tid  = threadIdx.x;
    const int wid  = tid >> 5, lane = tid & 31;
    const int gid  = lane >> 2, tig = lane & 3;
    const int bid  = blockIdx.x;

    const int nt = (bid < NTILE) ? ((NTILE - 1 - bid) / GRID + 1) : 0;
    const int nG = nt * NCHUNK;

    float acc[4][8][4];
#pragma unroll
    for (int m = 0; m < 4; m++)
#pragma unroll
        for (int n = 0; n < 8; n++)
#pragma unroll
            for (int q = 0; q < 4; q++) acc[m][n][q] = 0.f;

    // issue one sixth of chunk G's cp.asyncs (part 0..5); commit in part 5.
    auto issuePart = [&](int G, int part) {
        int tau = bid + (G >> 4) * GRID;
        if (tau < NTILE) {
            int ch  = G & 15;
            int ti  = tau & 31;
            int cog = (tau >> 5) & 7;
            int bb  = tau >> 8;
            int co0 = cog * MCO;
            int t0  = ti * NTT;
            int ci0 = ch * CC;
            const __half* aBase = aA + (size_t)bb * TT * CCH;
            const uint32_t sb = sbase + (uint32_t)(G % NSTAGE) * STAGE;
            int uend = (part + 1) * SEGP;
            for (int u = part * SEGP + tid; u < uend; u += CTN) {
                if (u < 768) {
                    int tile = u >> 8;
                    int rem  = u & 255;
                    int row  = rem >> 2;
                    int seg  = rem & 3;
                    const __half* src =
                        Wsp + ((size_t)(tile * CCH + co0 + row)) * CCH + ci0 + seg * 8;
                    cp16(sb + tile * A_TILE + row * ROWB + seg * 16, src, true);
                } else {
                    int u2  = u - 768;
                    int row = u2 >> 2;
                    int seg = u2 & 3;
                    int t   = t0 - 1 + row;
                    bool ok = (t >= 0 && t < TT && row < NTT + 2);
                    int tc  = ok ? t : 0;
                    const __half* src = aBase + (size_t)tc * CCH + ci0 + seg * 8;
                    cp16(sb + SM_BOFF + row * ROWB + seg * 16, src, ok);
                }
            }
        }
        if (part == 5) cp_commit();
    };
    auto issueAll = [&](int G) {
#pragma unroll
        for (int p = 0; p < 6; p++) issuePart(G, p);
    };

    issueAll(0);
    issueAll(1);

    const uint32_t aoffb = (uint32_t)((lane & 15) * ROWB + (lane >> 4) * 16);
    const uint32_t boffb = (uint32_t)(((lane & 7) + ((lane >> 4) << 3) + wid * 64) * ROWB
                                      + ((lane >> 3) & 1) * 16);

    for (int G = 0; G < nG; G++) {
        cp_wait<1>();
        __syncthreads();

        const uint32_t sb = sbase + (uint32_t)(G % NSTAGE) * STAGE;
        const uint32_t abase = sb + aoffb;
        const uint32_t bbase = sb + SM_BOFF + boffb;
#pragma unroll
        for (int ks = 0; ks < 2; ks++) {
#pragma unroll
            for (int tap = 0; tap < 3; tap++) {
                uint32_t bq[4][4];
#pragma unroll
                for (int np = 0; np < 4; np++)
                    ldx4(bq[np], bbase + (uint32_t)((np * 16 + tap) * ROWB + ks * 32));
#pragma unroll
                for (int m = 0; m < 4; m++) {
                    uint32_t af[4];
                    ldx4(af, abase + (uint32_t)(tap * A_TILE + m * 16 * ROWB + ks * 32));
#pragma unroll
                    for (int np = 0; np < 4; np++) {
                        mma16816(acc[m][2 * np],     af, &bq[np][0]);
                        mma16816(acc[m][2 * np + 1], af, &bq[np][2]);
                    }
                }
                issuePart(G + 2, ks * 3 + tap);   // uniform 6-way interleave
            }
        }

        if ((G & 15) == 15) {
            int tau = bid + (G >> 4) * GRID;
            int ti  = tau & 31;
            int cog = (tau >> 5) & 7;
            int bb  = tau >> 8;
            int co0 = cog * MCO;
            int t0  = ti * NTT;

            if (FUSE) {
                // ---- phase 0: all warps done reading stage G ----
                __syncthreads();
                const uint32_t ep = sbase + (uint32_t)(G % NSTAGE) * STAGE;
                // ---- phase 1: STS c1 tile fp16 [co][t] + edge column dump ----
#pragma unroll
                for (int m = 0; m < 4; m++) {
                    int r0 = m * 16 + gid, r1 = r0 + 8;
                    float b0 = bias[co0 + r0], b1 = bias[co0 + r1];
#pragma unroll
                    for (int n = 0; n < 8; n++) {
                        int tl = wid * 64 + n * 8 + 2 * tig;
                        float v00 = acc[m][n][0] + b0, v01 = acc[m][n][1] + b0;
                        float v10 = acc[m][n][2] + b1, v11 = acc[m][n][3] + b1;
                        __half2 h0 = __floats2half2_rn(v00, v01);
                        __half2 h1 = __floats2half2_rn(v10, v11);
                        sts32(ep + (uint32_t)(r0 * EPIT + tl * 2), *(uint32_t*)&h0);
                        sts32(ep + (uint32_t)(r1 * EPIT + tl * 2), *(uint32_t*)&h1);
                        if (wid == 0 && n == 0 && tig == 0) {       // t_loc 0,1
                            size_t eb = ((size_t)(bb * 32 + ti) * 4) * CCH;
                            edgeOut[eb + co0 + r0]       = __float2half(v00);
                            edgeOut[eb + CCH + co0 + r0] = __float2half(v01);
                            edgeOut[eb + co0 + r1]       = __float2half(v10);
                            edgeOut[eb + CCH + co0 + r1] = __float2half(v11);
                        }
                        if (wid == 3 && n == 7 && tig == 3) {       // t_loc 254,255
                            size_t eb = ((size_t)(bb * 32 + ti) * 4 + 2) * CCH;
                            edgeOut[eb + co0 + r0]       = __float2half(v00);
                            edgeOut[eb + CCH + co0 + r0] = __float2half(v01);
                            edgeOut[eb + co0 + r1]       = __float2half(v10);
                            edgeOut[eb + CCH + co0 + r1] = __float2half(v11);
                        }
                    }
                }
                __syncthreads();
                // ---- phase 2: act2 on tile, transposed coalesced store ----
                {
                    int tb  = tid >> 3;            // t-block (16 t each)
                    int cig = (tid & 7) * 8;       // 8 ci rows
                    uint32_t outw[16][4];
#pragma unroll
                    for (int j = 0; j < 4; j++) {
                        int ra = cig + 2 * j;
                        uint32_t pa = ep + (uint32_t)(ra * EPIT + tb * 32);
                        uint32_t pb = pa + EPIT;
                        float fa[18], fb[18];
                        q8f(lds128(pa), fa + 1); q8f(lds128(pa + 16), fa + 9);
                        q8f(lds128(pb), fb + 1); q8f(lds128(pb + 16), fb + 9);
                        fa[0]  = h2f16(lds16u(tb ? pa - 2 : pa));
                        fb[0]  = h2f16(lds16u(tb ? pb - 2 : pb));
                        fa[17] = h2f16(lds16u(pa + 32));
                        fb[17] = h2f16(lds16u(pb + 32));
                        float aaA = a2[co0 + ra],     biA = 0.5f * binv[co0 + ra];
                        float aaB = a2[co0 + ra + 1], biB = 0.5f * binv[co0 + ra + 1];
#pragma unroll
                        for (int s = 0; s < 16; s++) {
                            float u0A = fmaf(0.25f, fa[s],     0.75f * fa[s + 1]);
                            float u1A = fmaf(0.25f, fa[s + 2], 0.75f * fa[s + 1]);
                            float u0B = fmaf(0.25f, fb[s],     0.75f * fb[s + 1]);
                            float u1B = fmaf(0.25f, fb[s + 2], 0.75f * fb[s + 1]);
                            float yA = fmaf(0.5f, u0A + u1A,
                                (2.f - __cosf(aaA * u0A) - __cosf(aaA * u1A)) * biA);
                            float yB = fmaf(0.5f, u0B + u1B,
                                (2.f - __cosf(aaB * u0B) - __cosf(aaB * u1B)) * biB);
                            __half2 hp = __floats2half2_rn(yA, yB);
                            outw[s][j] = *(uint32_t*)&hp;
                        }
                    }
                    // unconditional stores: t%256==0/255 overwritten by edge kernel
#pragma unroll
                    for (int s = 0; s < 16; s++) {
                        int tl = tb * 16 + s;
                        __half* dst = actOut + ((size_t)bb * TT + t0 + tl) * CCH
                                      + co0 + cig;
                        *(uint4*)dst = make_uint4(outw[s][0], outw[s][1],
                                                  outw[s][2], outw[s][3]);
                    }
                }
                // ---- zero accumulators for next tile ----
#pragma unroll
                for (int m = 0; m < 4; m++)
#pragma unroll
                    for (int n = 0; n < 8; n++)
#pragma unroll
                        for (int q = 0; q < 4; q++) acc[m][n][q] = 0.f;
            } else {
                // ---- conv2 epilogue: fp32 + residual ----
#pragma unroll
                for (int m = 0; m < 4; m++) {
                    int r0 = co0 + m * 16 + gid;
                    int r1 = r0 + 8;
                    float b0 = bias[r0], b1 = bias[r1];
                    size_t o0 = ((size_t)(bb * CCH + r0)) * TT + t0;
                    size_t o1 = ((size_t)(bb * CCH + r1)) * TT + t0;
#pragma unroll
                    for (int n = 0; n < 8; n++) {
                        int tof = wid * 64 + n * 8 + 2 * tig;
                        float2 rv0 = *(const float2*)(resid + o0 + tof);
                        float2 rv1 = *(const float2*)(resid + o1 + tof);
                        *(float2*)(fOut + o0 + tof) =
                            make_float2(acc[m][n][0] + b0 + rv0.x,
                                        acc[m][n][1] + b0 + rv0.y);
                        *(float2*)(fOut + o1 + tof) =
                            make_float2(acc[m][n][2] + b1 + rv1.x,
                                        acc[m][n][3] + b1 + rv1.y);
#pragma unroll
                        for (int q = 0; q < 4; q++) acc[m][n][q] = 0.f;
                    }
                }
            }
        }
    }
}

// ---------------- kernel 4: act2 for tile-edge columns --------------------------
__global__ void edge_act_kernel(const __half* __restrict__ edge,
                                const float* __restrict__ a2,
                                const float* __restrict__ binv,
                                __half* __restrict__ actOut)
{
    int k = blockIdx.x, b = blockIdx.y;
    int ci = threadIdx.x * 2;
    float2 aa = make_float2(a2[ci], a2[ci + 1]);
    float2 bi = make_float2(0.5f * binv[ci], 0.5f * binv[ci + 1]);

    auto ld2 = [&](int kk, int e) {
        const __half2* p = (const __half2*)(edge + ((size_t)((b * 32 + kk) * 4 + e)) * CCH + ci);
        return __half22float2(*p);
    };
    auto snake = [&](float2 xm, float2 x0, float2 xp, bool first) {
        float2 u0, u1, y;
        u0.x = first ? x0.x : fmaf(0.25f, xm.x, 0.75f * x0.x);
        u0.y = first ? x0.y : fmaf(0.25f, xm.y, 0.75f * x0.y);
        u1.x = fmaf(0.25f, xp.x, 0.75f * x0.x);
        u1.y = fmaf(0.25f, xp.y, 0.75f * x0.y);
        y.x = fmaf(0.5f, u0.x + u1.x,
                   (2.f - __cosf(aa.x * u0.x) - __cosf(aa.x * u1.x)) * bi.x);
        y.y = fmaf(0.5f, u0.y + u1.y,
                   (2.f - __cosf(aa.y * u0.y) - __cosf(aa.y * u1.y)) * bi.y);
        return y;
    };

    // t = k*256  (e0; xm = prev tile e3)
    {
        float2 x0 = ld2(k, 0), xp = ld2(k, 1);
        float2 xm = (k > 0) ? ld2(k - 1, 3) : x0;
        float2 y = snake(xm, x0, xp, k == 0);
        *(__half2*)(actOut + ((size_t)b * TT + k * 256) * CCH + ci) =
            __floats2half2_rn(y.x, y.y);
    }
    // t = k*256 + 255  (e3; xp = next tile e0, clamp at global end)
    {
        float2 xm = ld2(k, 2), x0 = ld2(k, 3);
        float2 xp = (k < 31) ? ld2(k + 1, 0) : x0;
        float2 y = snake(xm, x0, xp, false);
        *(__half2*)(actOut + ((size_t)b * TT + k * 256 + 255) * CCH + ci) =
            __floats2half2_rn(y.x, y.y);
    }
}

// ---------------------------------- launch ---------------------------------------
extern "C" void kernel_launch(void* const* d_in, const int* in_sizes, int n_in,
                              void* d_out, int out_size)
{
    const float* x      = (const float*)d_in[0];
    const float* v1     = (const float*)d_in[1];
    const float* g1     = (const float*)d_in[2];
    const float* bias1  = (const float*)d_in[3];
    const float* v2     = (const float*)d_in[4];
    const float* g2     = (const float*)d_in[5];
    const float* bias2  = (const float*)d_in[6];
    const float* alpha1 = (const float*)d_in[7];
    const float* beta1  = (const float*)d_in[8];
    const float* alpha2 = (const float*)d_in[9];
    const float* beta2  = (const float*)d_in[10];
    float* out = (float*)d_out;

    __half *aA, *aB, *eg, *w1, *w2;
    float *a2c, *binv;
    cudaGetSymbolAddress((void**)&aA,   g_actT);
    cudaGetSymbolAddress((void**)&aB,   g_actT2);
    cudaGetSymbolAddress((void**)&eg,   g_edge);
    cudaGetSymbolAddress((void**)&w1,   g_w1);
    cudaGetSymbolAddress((void**)&w2,   g_w2);
    cudaGetSymbolAddress((void**)&a2c,  g_a2c);
    cudaGetSymbolAddress((void**)&binv, g_binv);

    static bool attr_set = false;
    if (!attr_set) {
        cudaFuncSetAttribute(conv_mma_kernel<true>,
                             cudaFuncAttributeMaxDynamicSharedMemorySize, SM_TOTAL);
        cudaFuncSetAttribute(conv_mma_kernel<false>,
                             cudaFuncAttributeMaxDynamicSharedMemorySize, SM_TOTAL);
        attr_set = true;
    }

    dim3 wgrid(CCH, 2);
    wnorm_kernel<<<wgrid, 256>>>(v1, g1, alpha1, beta1,
                                 v2, g2, alpha2, beta2,
                                 w1, w2, a2c, binv);

    dim3 agrid(TT / ATT, CCH / ATI, BSZ);
    snake_actT_kernel<<<agrid, 256>>>(x, a2c, binv, aA);

    // conv1 (+fused act2 interior) -> actT2 ; edge cols -> g_edge
    conv_mma_kernel<true><<<GRID, CTN, SM_TOTAL>>>(
        aA, w1, bias1, nullptr, a2c + CCH, binv + CCH, aB, eg, nullptr);

    // act2 edge columns (overwrites t%256==0/255 of actT2)
    edge_act_kernel<<<dim3(32, BSZ), 256>>>(eg, a2c + CCH, binv + CCH, aB);

    // conv2 + residual -> out
    conv_mma_kernel<false><<<GRID, CTN, SM_TOTAL>>>(
        aB, w2, bias2, x, nullptr, nullptr, nullptr, nullptr, out);
}